// round 1
// baseline (speedup 1.0000x reference)
#include <cuda_runtime.h>
#include <math.h>

// ---------------- problem constants ----------------
#define MWIN   8192
#define KTOK   32
#define TOK    33          // K + G
#define CCH    256
#define HEADS  8
#define HDIM   32
#define NPTS   (MWIN * KTOK)        // 262144
#define ROWS   (MWIN * TOK)         // 270336
#define HID    1024
#define NEIGH  27
#define POS_BND 25
#define RPE_NUM 51                  // 2*25+1
#define C3     768

// ---------------- scratch (static device globals; no cudaMalloc) ----------------
__device__ float g_xbuf[(size_t)ROWS * CCH];   // residual stream x
__device__ float g_hbuf[(size_t)ROWS * CCH];   // LN output / attention output
__device__ float g_big [(size_t)ROWS * HID];   // qkv (uses 768 cols) / mlp hidden (1024 cols)

// ---------------- kernel 1: CPE gather + residual, build x ----------------
__global__ void __launch_bounds__(256) cpe_kernel(
    const float* __restrict__ data, const float* __restrict__ rt,
    const int* __restrict__ neighbors, const float* __restrict__ cpe_w,
    const float* __restrict__ cpe_scale, const float* __restrict__ cpe_bias)
{
    int bid = blockIdx.x;
    int c = threadIdx.x;
    if (bid >= NPTS) {
        int m = bid - NPTS;
        g_xbuf[((size_t)m * TOK) * CCH + c] = rt[(size_t)m * CCH + c];
        return;
    }
    __shared__ int nb[NEIGH];
    if (threadIdx.x < NEIGH) nb[threadIdx.x] = neighbors[(size_t)bid * NEIGH + threadIdx.x];
    __syncthreads();
    float acc = 0.f;
    #pragma unroll
    for (int j = 0; j < NEIGH; j++)
        acc += data[(size_t)nb[j] * CCH + c] * cpe_w[j * CCH + c];
    float v = data[(size_t)bid * CCH + c] + acc * cpe_scale[c] + cpe_bias[c];
    int m = bid >> 5, k = bid & 31;
    g_xbuf[((size_t)m * TOK + 1 + k) * CCH + c] = v;
}

// ---------------- layernorm: one warp per row of 256 ----------------
__global__ void __launch_bounds__(256) ln_kernel(
    const float* __restrict__ in, float* __restrict__ out,
    const float* __restrict__ gam, const float* __restrict__ bet)
{
    int warp = threadIdx.x >> 5, lane = threadIdx.x & 31;
    size_t row = (size_t)blockIdx.x * 8 + warp;
    const float* r = in + row * CCH;
    float v[8];
    float s = 0.f;
    #pragma unroll
    for (int i = 0; i < 8; i++) { v[i] = r[lane + i * 32]; s += v[i]; }
    #pragma unroll
    for (int o = 16; o; o >>= 1) s += __shfl_xor_sync(0xffffffffu, s, o);
    float mean = s * (1.f / 256.f);
    float vs = 0.f;
    #pragma unroll
    for (int i = 0; i < 8; i++) { float d = v[i] - mean; vs += d * d; }
    #pragma unroll
    for (int o = 16; o; o >>= 1) vs += __shfl_xor_sync(0xffffffffu, vs, o);
    float rstd = rsqrtf(vs * (1.f / 256.f) + 1e-5f);
    float* w = out + row * CCH;
    #pragma unroll
    for (int i = 0; i < 8; i++) {
        int c = lane + i * 32;
        w[c] = (v[i] - mean) * rstd * gam[c] + bet[c];
    }
}

// ---------------- SGEMM: 128x128 tile, BK=8, 256 threads, 8x8 per thread ----------------
// MODE 0: out = A@B + bias
// MODE 1: out = res + A@B + bias            (res/out stride = Ndim; in-place OK)
// MODE 2: out = gelu(A@B + bias)            (exact erf gelu)
// MODE 3: out = res + A@B + bias, scattered into d_out layout [data_out | rt_out]
template<int MODE>
__global__ void __launch_bounds__(256) sgemm_kernel(
    const float* __restrict__ A, const float* __restrict__ B,
    const float* __restrict__ bias, float* __restrict__ Cout,
    const float* __restrict__ res, int Kdim, int Ndim)
{
    __shared__ float As[8][128];
    __shared__ float Bs[8][128];
    int tid = threadIdx.x;
    int tx = tid & 15, ty = tid >> 4;
    size_t rowBase = (size_t)blockIdx.y * 128;
    int colBase = blockIdx.x * 128;

    int ar  = tid >> 1;            // 0..127
    int ac  = (tid & 1) * 4;       // 0 or 4
    int bkr = tid >> 5;            // 0..7
    int bcc = (tid & 31) * 4;      // 0..124

    const float* Aptr = A + rowBase * Kdim;
    float acc[8][8];
    #pragma unroll
    for (int i = 0; i < 8; i++)
        #pragma unroll
        for (int j = 0; j < 8; j++) acc[i][j] = 0.f;

    for (int k0 = 0; k0 < Kdim; k0 += 8) {
        float4 a4 = *(const float4*)(Aptr + (size_t)ar * Kdim + k0 + ac);
        As[ac + 0][ar] = a4.x; As[ac + 1][ar] = a4.y;
        As[ac + 2][ar] = a4.z; As[ac + 3][ar] = a4.w;
        float4 b4 = *(const float4*)(B + (size_t)(k0 + bkr) * Ndim + colBase + bcc);
        *(float4*)&Bs[bkr][bcc] = b4;
        __syncthreads();
        #pragma unroll
        for (int kk = 0; kk < 8; kk++) {
            float ra[8], rb[8];
            #pragma unroll
            for (int i = 0; i < 8; i++) ra[i] = As[kk][ty + i * 16];
            #pragma unroll
            for (int j = 0; j < 8; j++) rb[j] = Bs[kk][tx + j * 16];
            #pragma unroll
            for (int i = 0; i < 8; i++)
                #pragma unroll
                for (int j = 0; j < 8; j++) acc[i][j] += ra[i] * rb[j];
        }
        __syncthreads();
    }

    #pragma unroll
    for (int i = 0; i < 8; i++) {
        size_t row = rowBase + ty + i * 16;
        #pragma unroll
        for (int j = 0; j < 8; j++) {
            int col = colBase + tx + j * 16;
            float v = acc[i][j] + bias[col];
            if (MODE == 1) {
                v += res[row * Ndim + col];
                Cout[row * Ndim + col] = v;
            } else if (MODE == 2) {
                v = 0.5f * v * (1.0f + erff(v * 0.70710678118654752f));
                Cout[row * Ndim + col] = v;
            } else if (MODE == 3) {
                v += res[row * CCH + col];
                size_t m = row / TOK;
                int t = (int)(row - m * TOK);
                if (t == 0)
                    Cout[(size_t)NPTS * CCH + m * CCH + col] = v;
                else
                    Cout[(m * KTOK + (size_t)(t - 1)) * CCH + col] = v;
            } else {
                Cout[row * Ndim + col] = v;
            }
        }
    }
}

// ---------------- fused per-window attention ----------------
// smem: qkv tile (33*768) + scores (8*33*33) + rpe table (153*8) = 141120 B
#define ATTN_SMEM ((TOK * C3 + HEADS * TOK * TOK + 3 * RPE_NUM * HEADS) * 4)

__global__ void __launch_bounds__(256) attn_kernel(
    const float* __restrict__ qkv, const int* __restrict__ rel_pos,
    const float* __restrict__ mask, const float* __restrict__ rpe_table,
    float* __restrict__ outbuf)
{
    extern __shared__ float sm[];
    float* sqkv  = sm;                        // 33*768
    float* sscore = sm + TOK * C3;            // 8*33*33
    float* stab  = sscore + HEADS * TOK * TOK; // 153*8

    int m = blockIdx.x, tid = threadIdx.x;
    const float* src = qkv + (size_t)m * TOK * C3;
    for (int i = tid; i < TOK * C3 / 4; i += 256)
        ((float4*)sqkv)[i] = ((const float4*)src)[i];
    for (int i = tid; i < 3 * RPE_NUM * HEADS; i += 256) stab[i] = rpe_table[i];
    __syncthreads();

    const float scale = 0.17677669529663687f;   // 1/sqrt(32)

    // scores + rpe + mask
    for (int idx = tid; idx < HEADS * TOK * TOK; idx += 256) {
        int j = idx % TOK;
        int ih = idx / TOK;
        int i = ih % TOK;
        int h = ih / TOK;
        const float* qp = sqkv + i * C3 + h * HDIM;
        const float* kp = sqkv + j * C3 + CCH + h * HDIM;
        float s = 0.f;
        #pragma unroll
        for (int d = 0; d < HDIM; d++) s += qp[d] * kp[d];
        s *= scale;
        if (i > 0 && j > 0) {
            const int* rp = rel_pos + (((size_t)m * KTOK + (i - 1)) * KTOK + (j - 1)) * 3;
            #pragma unroll
            for (int dd = 0; dd < 3; dd++) {
                int r = rp[dd];
                r = min(max(r, -POS_BND), POS_BND);
                s += stab[(r + POS_BND + dd * RPE_NUM) * HEADS + h];
            }
        }
        s += mask[((size_t)m * TOK + i) * TOK + j];
        sscore[(h * TOK + i) * TOK + j] = s;
    }
    __syncthreads();

    // softmax over 33 cols; one warp per (h,i) row
    int lane = tid & 31, warp = tid >> 5;
    for (int r = warp; r < HEADS * TOK; r += 8) {
        float* row = sscore + r * TOK;
        float x0 = row[lane];
        float x1 = (lane == 0) ? row[32] : -1e30f;
        float mx = fmaxf(x0, x1);
        #pragma unroll
        for (int o = 16; o; o >>= 1) mx = fmaxf(mx, __shfl_xor_sync(0xffffffffu, mx, o));
        float e0 = __expf(x0 - mx);
        float e1 = (lane == 0) ? __expf(x1 - mx) : 0.f;
        float s = e0 + e1;
        #pragma unroll
        for (int o = 16; o; o >>= 1) s += __shfl_xor_sync(0xffffffffu, s, o);
        float inv = 1.f / s;
        row[lane] = e0 * inv;
        if (lane == 0) row[32] = e1 * inv;
    }
    __syncthreads();

    // out[i][h][d] = sum_j scores[h][i][j] * v[j][h][d]; thread = (h=tid/32, d=tid%32)
    int h = tid >> 5, d = tid & 31;
    const float* vbase = sqkv + 2 * CCH + h * HDIM + d;
    float* ob = outbuf + ((size_t)m * TOK) * CCH + h * HDIM + d;
    for (int i = 0; i < TOK; i++) {
        const float* srow = sscore + (h * TOK + i) * TOK;
        float acc = 0.f;
        #pragma unroll
        for (int j = 0; j < TOK; j++) acc += srow[j] * vbase[(size_t)j * C3];
        ob[(size_t)i * CCH] = acc;
    }
}

// ---------------- host launcher ----------------
extern "C" void kernel_launch(void* const* d_in, const int* in_sizes, int n_in,
                              void* d_out, int out_size)
{
    const float* data      = (const float*)d_in[0];
    const float* rt        = (const float*)d_in[1];
    const int*   neighbors = (const int*)  d_in[2];
    const int*   rel_pos   = (const int*)  d_in[3];
    const float* mask      = (const float*)d_in[4];
    const float* cpe_w     = (const float*)d_in[5];
    const float* cpe_scale = (const float*)d_in[6];
    const float* cpe_bias  = (const float*)d_in[7];
    const float* ln1_g     = (const float*)d_in[8];
    const float* ln1_b     = (const float*)d_in[9];
    const float* qkv_w     = (const float*)d_in[10];
    const float* qkv_b     = (const float*)d_in[11];
    const float* rpe_table = (const float*)d_in[12];
    const float* proj_w    = (const float*)d_in[13];
    const float* proj_b    = (const float*)d_in[14];
    const float* ln2_g     = (const float*)d_in[15];
    const float* ln2_b     = (const float*)d_in[16];
    const float* mlp_w1    = (const float*)d_in[17];
    const float* mlp_b1    = (const float*)d_in[18];
    const float* mlp_w2    = (const float*)d_in[19];
    const float* mlp_b2    = (const float*)d_in[20];
    float* out = (float*)d_out;

    float* xbuf; cudaGetSymbolAddress((void**)&xbuf, g_xbuf);
    float* hbuf; cudaGetSymbolAddress((void**)&hbuf, g_hbuf);
    float* big;  cudaGetSymbolAddress((void**)&big,  g_big);

    cudaFuncSetAttribute(attn_kernel, cudaFuncAttributeMaxDynamicSharedMemorySize, ATTN_SMEM);

    // 1. CPE + residual -> x ; copy rt row
    cpe_kernel<<<NPTS + MWIN, 256>>>(data, rt, neighbors, cpe_w, cpe_scale, cpe_bias);

    // 2. LN1
    ln_kernel<<<ROWS / 8, 256>>>(xbuf, hbuf, ln1_g, ln1_b);

    // 3. QKV = h @ qkv_w + b  (270336 x 256 x 768)
    {
        dim3 grid(C3 / 128, ROWS / 128);
        sgemm_kernel<0><<<grid, 256>>>(hbuf, qkv_w, qkv_b, big, nullptr, CCH, C3);
    }

    // 4. fused attention per window -> hbuf
    attn_kernel<<<MWIN, 256, ATTN_SMEM>>>(big, rel_pos, mask, rpe_table, hbuf);

    // 5. x = x + attnout @ proj_w + proj_b  (in-place on xbuf)
    {
        dim3 grid(CCH / 128, ROWS / 128);
        sgemm_kernel<1><<<grid, 256>>>(hbuf, proj_w, proj_b, xbuf, xbuf, CCH, CCH);
    }

    // 6. LN2
    ln_kernel<<<ROWS / 8, 256>>>(xbuf, hbuf, ln2_g, ln2_b);

    // 7. hidden = gelu(h @ mlp_w1 + b1)  (270336 x 256 x 1024)
    {
        dim3 grid(HID / 128, ROWS / 128);
        sgemm_kernel<2><<<grid, 256>>>(hbuf, mlp_w1, mlp_b1, big, nullptr, CCH, HID);
    }

    // 8. out = x + hidden @ mlp_w2 + b2, scattered to [data_out | rt_out]
    {
        dim3 grid(CCH / 128, ROWS / 128);
        sgemm_kernel<3><<<grid, 256>>>(big, mlp_w2, mlp_b2, out, xbuf, HID, CCH);
    }
}

// round 2
// speedup vs baseline: 1.9079x; 1.9079x over previous
#include <cuda_runtime.h>
#include <math.h>
#include <stdint.h>

// ---------------- problem constants ----------------
#define MWIN   8192
#define KTOK   32
#define TOK    33          // K + G
#define CCH    256
#define HEADS  8
#define HDIM   32
#define NPTS   (MWIN * KTOK)        // 262144
#define ROWS   (MWIN * TOK)         // 270336
#define HID    1024
#define NEIGH  27
#define POS_BND 25
#define RPE_NUM 51                  // 2*25+1
#define C3     768

// ---------------- scratch (static device globals; no cudaMalloc) ----------------
__device__ float g_xbuf[(size_t)ROWS * CCH];   // residual stream x
__device__ float g_hbuf[(size_t)ROWS * CCH];   // LN output / attention output
__device__ float g_big [(size_t)ROWS * HID];   // qkv (768 cols) / mlp hidden (1024 cols)

// ---------------- kernel 1: CPE gather + residual, build x ----------------
__global__ void __launch_bounds__(256) cpe_kernel(
    const float* __restrict__ data, const float* __restrict__ rt,
    const int* __restrict__ neighbors, const float* __restrict__ cpe_w,
    const float* __restrict__ cpe_scale, const float* __restrict__ cpe_bias)
{
    int bid = blockIdx.x;
    int c = threadIdx.x;
    if (bid >= NPTS) {
        int m = bid - NPTS;
        g_xbuf[((size_t)m * TOK) * CCH + c] = rt[(size_t)m * CCH + c];
        return;
    }
    __shared__ int nb[NEIGH];
    if (threadIdx.x < NEIGH) nb[threadIdx.x] = neighbors[(size_t)bid * NEIGH + threadIdx.x];
    __syncthreads();
    float acc = 0.f;
    #pragma unroll
    for (int j = 0; j < NEIGH; j++)
        acc += data[(size_t)nb[j] * CCH + c] * cpe_w[j * CCH + c];
    float v = data[(size_t)bid * CCH + c] + acc * cpe_scale[c] + cpe_bias[c];
    int m = bid >> 5, k = bid & 31;
    g_xbuf[((size_t)m * TOK + 1 + k) * CCH + c] = v;
}

// ---------------- layernorm: one warp per row of 256 ----------------
__global__ void __launch_bounds__(256) ln_kernel(
    const float* __restrict__ in, float* __restrict__ out,
    const float* __restrict__ gam, const float* __restrict__ bet)
{
    int warp = threadIdx.x >> 5, lane = threadIdx.x & 31;
    size_t row = (size_t)blockIdx.x * 8 + warp;
    const float* r = in + row * CCH;
    float v[8];
    float s = 0.f;
    #pragma unroll
    for (int i = 0; i < 8; i++) { v[i] = r[lane + i * 32]; s += v[i]; }
    #pragma unroll
    for (int o = 16; o; o >>= 1) s += __shfl_xor_sync(0xffffffffu, s, o);
    float mean = s * (1.f / 256.f);
    float vs = 0.f;
    #pragma unroll
    for (int i = 0; i < 8; i++) { float d = v[i] - mean; vs += d * d; }
    #pragma unroll
    for (int o = 16; o; o >>= 1) vs += __shfl_xor_sync(0xffffffffu, vs, o);
    float rstd = rsqrtf(vs * (1.f / 256.f) + 1e-5f);
    float* w = out + row * CCH;
    #pragma unroll
    for (int i = 0; i < 8; i++) {
        int c = lane + i * 32;
        w[c] = (v[i] - mean) * rstd * gam[c] + bet[c];
    }
}

// ---------------- tf32 tensor-core GEMM ----------------
// 128x128x32 tiles, 256 threads (8 warps, 2x4), warp tile 64x32 via m16n8k8.
// MODE 0: out = A@B + bias
// MODE 1: out = res + A@B + bias   (res/out stride = Ndim; in-place OK)
// MODE 2: out = gelu(A@B + bias)
// MODE 3: out = res + A@B + bias, scattered into d_out layout [data_out | rt_out]

__device__ __forceinline__ uint32_t f2tf32(float f) {
    uint32_t u;
    asm("cvt.rna.tf32.f32 %0, %1;" : "=r"(u) : "f"(f));
    return u;
}

#define CP_ASYNC16(dst_u32, src_ptr) \
    asm volatile("cp.async.cg.shared.global [%0], [%1], 16;\n" :: "r"(dst_u32), "l"(src_ptr))
#define CP_COMMIT() asm volatile("cp.async.commit_group;\n")
#define CP_WAIT1()  asm volatile("cp.async.wait_group 1;\n")

#define BM 128
#define BN 128
#define BKQ 32
#define ASTRIDE 36    // BK + 4  -> frag-load bank = (4g+t), conflict free
#define BSTRIDE 132   // BN + 4  -> frag-load bank = (4t+g), conflict free
#define GEMM_SMEM ((2 * BM * ASTRIDE + 2 * BKQ * BSTRIDE) * 4)

template<int MODE>
__global__ void __launch_bounds__(256) tgemm_kernel(
    const float* __restrict__ A, const float* __restrict__ B,
    const float* __restrict__ bias, float* __restrict__ Cout,
    const float* __restrict__ res, int Kdim, int Ndim)
{
    extern __shared__ float smem[];
    float* Asm = smem;                       // [2][BM][ASTRIDE]
    float* Bsm = smem + 2 * BM * ASTRIDE;    // [2][BKQ][BSTRIDE]

    int tid = threadIdx.x;
    int warp = tid >> 5, lane = tid & 31;
    int g = lane >> 2, t = lane & 3;
    int wm = (warp >> 2) * 64;   // warp row offset
    int wn = (warp & 3) * 32;    // warp col offset

    size_t rowBase = (size_t)blockIdx.y * BM;
    int colBase = blockIdx.x * BN;

    // global tile load indices
    int arow = tid >> 3;          // 0..31 (+32*pass)
    int acol = (tid & 7) * 4;     // 0,4,..28
    int brow = tid >> 5;          // 0..7 (+8*pass)
    int bcol = (tid & 31) * 4;    // 0..124

    const float* Ag = A + rowBase * Kdim;

    float acc[4][4][4];
    #pragma unroll
    for (int mt = 0; mt < 4; mt++)
        #pragma unroll
        for (int nt = 0; nt < 4; nt++)
            #pragma unroll
            for (int i = 0; i < 4; i++) acc[mt][nt][i] = 0.f;

    auto loadStage = [&](int s, int k0) {
        float* as = Asm + s * BM * ASTRIDE;
        float* bs = Bsm + s * BKQ * BSTRIDE;
        #pragma unroll
        for (int p = 0; p < 4; p++) {
            int r = arow + p * 32;
            uint32_t dst = (uint32_t)__cvta_generic_to_shared(&as[r * ASTRIDE + acol]);
            const float* src = Ag + (size_t)r * Kdim + k0 + acol;
            CP_ASYNC16(dst, src);
        }
        #pragma unroll
        for (int p = 0; p < 4; p++) {
            int kk = brow + p * 8;
            uint32_t dst = (uint32_t)__cvta_generic_to_shared(&bs[kk * BSTRIDE + bcol]);
            const float* src = B + (size_t)(k0 + kk) * Ndim + colBase + bcol;
            CP_ASYNC16(dst, src);
        }
    };

    int KT = Kdim / BKQ;
    loadStage(0, 0);
    CP_COMMIT();

    for (int kt = 0; kt < KT; kt++) {
        if (kt + 1 < KT) loadStage((kt + 1) & 1, (kt + 1) * BKQ);
        CP_COMMIT();
        CP_WAIT1();
        __syncthreads();

        const float* as = Asm + (kt & 1) * BM * ASTRIDE;
        const float* bs = Bsm + (kt & 1) * BKQ * BSTRIDE;

        #pragma unroll
        for (int kk = 0; kk < 4; kk++) {
            int kb = kk * 8;
            uint32_t af[4][4], bf[4][2];
            #pragma unroll
            for (int mt = 0; mt < 4; mt++) {
                int m0 = wm + mt * 16;
                af[mt][0] = f2tf32(as[(m0 + g    ) * ASTRIDE + kb + t    ]);
                af[mt][1] = f2tf32(as[(m0 + g + 8) * ASTRIDE + kb + t    ]);
                af[mt][2] = f2tf32(as[(m0 + g    ) * ASTRIDE + kb + t + 4]);
                af[mt][3] = f2tf32(as[(m0 + g + 8) * ASTRIDE + kb + t + 4]);
            }
            #pragma unroll
            for (int nt = 0; nt < 4; nt++) {
                int n0 = wn + nt * 8;
                bf[nt][0] = f2tf32(bs[(kb + t    ) * BSTRIDE + n0 + g]);
                bf[nt][1] = f2tf32(bs[(kb + t + 4) * BSTRIDE + n0 + g]);
            }
            #pragma unroll
            for (int mt = 0; mt < 4; mt++)
                #pragma unroll
                for (int nt = 0; nt < 4; nt++) {
                    asm volatile(
                        "mma.sync.aligned.m16n8k8.row.col.f32.tf32.tf32.f32 "
                        "{%0,%1,%2,%3},{%4,%5,%6,%7},{%8,%9},{%0,%1,%2,%3};"
                        : "+f"(acc[mt][nt][0]), "+f"(acc[mt][nt][1]),
                          "+f"(acc[mt][nt][2]), "+f"(acc[mt][nt][3])
                        : "r"(af[mt][0]), "r"(af[mt][1]), "r"(af[mt][2]), "r"(af[mt][3]),
                          "r"(bf[nt][0]), "r"(bf[nt][1]));
                }
        }
        __syncthreads();
    }

    // epilogue: c0:(g,2t) c1:(g,2t+1) c2:(g+8,2t) c3:(g+8,2t+1)
    #pragma unroll
    for (int mt = 0; mt < 4; mt++) {
        #pragma unroll
        for (int nt = 0; nt < 4; nt++) {
            #pragma unroll
            for (int i = 0; i < 4; i++) {
                size_t row = rowBase + wm + mt * 16 + g + (i >> 1) * 8;
                int col = colBase + wn + nt * 8 + 2 * t + (i & 1);
                float v = acc[mt][nt][i] + bias[col];
                if (MODE == 1) {
                    v += res[row * Ndim + col];
                    Cout[row * Ndim + col] = v;
                } else if (MODE == 2) {
                    v = 0.5f * v * (1.0f + erff(v * 0.70710678118654752f));
                    Cout[row * Ndim + col] = v;
                } else if (MODE == 3) {
                    v += res[row * CCH + col];
                    size_t m = row / TOK;
                    int tt = (int)(row - m * TOK);
                    if (tt == 0)
                        Cout[(size_t)NPTS * CCH + m * CCH + col] = v;
                    else
                        Cout[(m * KTOK + (size_t)(tt - 1)) * CCH + col] = v;
                } else {
                    Cout[row * Ndim + col] = v;
                }
            }
        }
    }
}

// ---------------- fused per-window attention ----------------
#define ATTN_SMEM ((TOK * C3 + HEADS * TOK * TOK + 3 * RPE_NUM * HEADS) * 4)

__global__ void __launch_bounds__(256) attn_kernel(
    const float* __restrict__ qkv, const int* __restrict__ rel_pos,
    const float* __restrict__ mask, const float* __restrict__ rpe_table,
    float* __restrict__ outbuf)
{
    extern __shared__ float sm[];
    float* sqkv  = sm;                          // 33*768
    float* sscore = sm + TOK * C3;              // 8*33*33
    float* stab  = sscore + HEADS * TOK * TOK;  // 153*8

    int m = blockIdx.x, tid = threadIdx.x;
    const float* src = qkv + (size_t)m * TOK * C3;
    for (int i = tid; i < TOK * C3 / 4; i += 256)
        ((float4*)sqkv)[i] = ((const float4*)src)[i];
    for (int i = tid; i < 3 * RPE_NUM * HEADS; i += 256) stab[i] = rpe_table[i];
    __syncthreads();

    const float scale = 0.17677669529663687f;   // 1/sqrt(32)

    for (int idx = tid; idx < HEADS * TOK * TOK; idx += 256) {
        int j = idx % TOK;
        int ih = idx / TOK;
        int i = ih % TOK;
        int h = ih / TOK;
        const float* qp = sqkv + i * C3 + h * HDIM;
        const float* kp = sqkv + j * C3 + CCH + h * HDIM;
        float s = 0.f;
        #pragma unroll
        for (int d = 0; d < HDIM; d++) s += qp[d] * kp[d];
        s *= scale;
        if (i > 0 && j > 0) {
            const int* rp = rel_pos + (((size_t)m * KTOK + (i - 1)) * KTOK + (j - 1)) * 3;
            #pragma unroll
            for (int dd = 0; dd < 3; dd++) {
                int r = rp[dd];
                r = min(max(r, -POS_BND), POS_BND);
                s += stab[(r + POS_BND + dd * RPE_NUM) * HEADS + h];
            }
        }
        s += mask[((size_t)m * TOK + i) * TOK + j];
        sscore[(h * TOK + i) * TOK + j] = s;
    }
    __syncthreads();

    int lane = tid & 31, warp = tid >> 5;
    for (int r = warp; r < HEADS * TOK; r += 8) {
        float* row = sscore + r * TOK;
        float x0 = row[lane];
        float x1 = (lane == 0) ? row[32] : -1e30f;
        float mx = fmaxf(x0, x1);
        #pragma unroll
        for (int o = 16; o; o >>= 1) mx = fmaxf(mx, __shfl_xor_sync(0xffffffffu, mx, o));
        float e0 = __expf(x0 - mx);
        float e1 = (lane == 0) ? __expf(x1 - mx) : 0.f;
        float s = e0 + e1;
        #pragma unroll
        for (int o = 16; o; o >>= 1) s += __shfl_xor_sync(0xffffffffu, s, o);
        float inv = 1.f / s;
        row[lane] = e0 * inv;
        if (lane == 0) row[32] = e1 * inv;
    }
    __syncthreads();

    int h = tid >> 5, d = tid & 31;
    const float* vbase = sqkv + 2 * CCH + h * HDIM + d;
    float* ob = outbuf + ((size_t)m * TOK) * CCH + h * HDIM + d;
    for (int i = 0; i < TOK; i++) {
        const float* srow = sscore + (h * TOK + i) * TOK;
        float acc = 0.f;
        #pragma unroll
        for (int j = 0; j < TOK; j++) acc += srow[j] * vbase[(size_t)j * C3];
        ob[(size_t)i * CCH] = acc;
    }
}

// ---------------- host launcher ----------------
extern "C" void kernel_launch(void* const* d_in, const int* in_sizes, int n_in,
                              void* d_out, int out_size)
{
    const float* data      = (const float*)d_in[0];
    const float* rt        = (const float*)d_in[1];
    const int*   neighbors = (const int*)  d_in[2];
    const int*   rel_pos   = (const int*)  d_in[3];
    const float* mask      = (const float*)d_in[4];
    const float* cpe_w     = (const float*)d_in[5];
    const float* cpe_scale = (const float*)d_in[6];
    const float* cpe_bias  = (const float*)d_in[7];
    const float* ln1_g     = (const float*)d_in[8];
    const float* ln1_b     = (const float*)d_in[9];
    const float* qkv_w     = (const float*)d_in[10];
    const float* qkv_b     = (const float*)d_in[11];
    const float* rpe_table = (const float*)d_in[12];
    const float* proj_w    = (const float*)d_in[13];
    const float* proj_b    = (const float*)d_in[14];
    const float* ln2_g     = (const float*)d_in[15];
    const float* ln2_b     = (const float*)d_in[16];
    const float* mlp_w1    = (const float*)d_in[17];
    const float* mlp_b1    = (const float*)d_in[18];
    const float* mlp_w2    = (const float*)d_in[19];
    const float* mlp_b2    = (const float*)d_in[20];
    float* out = (float*)d_out;

    float* xbuf; cudaGetSymbolAddress((void**)&xbuf, g_xbuf);
    float* hbuf; cudaGetSymbolAddress((void**)&hbuf, g_hbuf);
    float* big;  cudaGetSymbolAddress((void**)&big,  g_big);

    cudaFuncSetAttribute(attn_kernel, cudaFuncAttributeMaxDynamicSharedMemorySize, ATTN_SMEM);
    cudaFuncSetAttribute(tgemm_kernel<0>, cudaFuncAttributeMaxDynamicSharedMemorySize, GEMM_SMEM);
    cudaFuncSetAttribute(tgemm_kernel<1>, cudaFuncAttributeMaxDynamicSharedMemorySize, GEMM_SMEM);
    cudaFuncSetAttribute(tgemm_kernel<2>, cudaFuncAttributeMaxDynamicSharedMemorySize, GEMM_SMEM);
    cudaFuncSetAttribute(tgemm_kernel<3>, cudaFuncAttributeMaxDynamicSharedMemorySize, GEMM_SMEM);

    // 1. CPE + residual -> x ; copy rt row
    cpe_kernel<<<NPTS + MWIN, 256>>>(data, rt, neighbors, cpe_w, cpe_scale, cpe_bias);

    // 2. LN1
    ln_kernel<<<ROWS / 8, 256>>>(xbuf, hbuf, ln1_g, ln1_b);

    // 3. QKV = h @ qkv_w + b  (270336 x 256 x 768)
    {
        dim3 grid(C3 / 128, ROWS / 128);
        tgemm_kernel<0><<<grid, 256, GEMM_SMEM>>>(hbuf, qkv_w, qkv_b, big, nullptr, CCH, C3);
    }

    // 4. fused attention per window -> hbuf
    attn_kernel<<<MWIN, 256, ATTN_SMEM>>>(big, rel_pos, mask, rpe_table, hbuf);

    // 5. x = x + attnout @ proj_w + proj_b  (in-place on xbuf)
    {
        dim3 grid(CCH / 128, ROWS / 128);
        tgemm_kernel<1><<<grid, 256, GEMM_SMEM>>>(hbuf, proj_w, proj_b, xbuf, xbuf, CCH, CCH);
    }

    // 6. LN2
    ln_kernel<<<ROWS / 8, 256>>>(xbuf, hbuf, ln2_g, ln2_b);

    // 7. hidden = gelu(h @ mlp_w1 + b1)  (270336 x 256 x 1024)
    {
        dim3 grid(HID / 128, ROWS / 128);
        tgemm_kernel<2><<<grid, 256, GEMM_SMEM>>>(hbuf, mlp_w1, mlp_b1, big, nullptr, CCH, HID);
    }

    // 8. out = x + hidden @ mlp_w2 + b2, scattered to [data_out | rt_out]
    {
        dim3 grid(CCH / 128, ROWS / 128);
        tgemm_kernel<3><<<grid, 256, GEMM_SMEM>>>(big, mlp_w2, mlp_b2, out, xbuf, HID, CCH);
    }
}

// round 4
// speedup vs baseline: 2.1131x; 1.1076x over previous
#include <cuda_runtime.h>
#include <cuda_fp16.h>
#include <math.h>
#include <stdint.h>

// ---------------- problem constants ----------------
#define MWIN   8192
#define KTOK   32
#define TOK    33          // K + G
#define CCH    256
#define HEADS  8
#define HDIM   32
#define NPTS   (MWIN * KTOK)        // 262144
#define ROWS   (MWIN * TOK)         // 270336
#define HID    1024
#define NEIGH  27
#define POS_BND 25
#define RPE_NUM 51
#define C3     768

// ---------------- scratch ----------------
__device__ float  g_xbuf [(size_t)ROWS * CCH];   // residual stream (fp32)
__device__ __half g_hbuf16[(size_t)ROWS * CCH];  // LN out / attn out (fp16)
__device__ __half g_big16 [(size_t)ROWS * HID];  // qkv / mlp hidden (fp16)
__device__ __half g_wT16  [768*256 + 256*256 + 1024*256 + 256*1024]; // W^T fp16

// ---------------- PTX helpers ----------------
__device__ __forceinline__ uint32_t smem_u32(const void* p) {
    uint32_t a;
    asm("{ .reg .u64 t; cvta.to.shared.u64 t, %1; cvt.u32.u64 %0, t; }" : "=r"(a) : "l"(p));
    return a;
}
#define CP_ASYNC16(dst_u32, src_ptr) \
    asm volatile("cp.async.cg.shared.global [%0], [%1], 16;\n" :: "r"(dst_u32), "l"(src_ptr))
#define CP_COMMIT() asm volatile("cp.async.commit_group;\n")
#define CP_WAIT(n)  asm volatile("cp.async.wait_group %0;\n" :: "n"(n))

#define LDSM_X4(r0,r1,r2,r3,a) \
    asm volatile("ldmatrix.sync.aligned.m8n8.x4.shared.b16 {%0,%1,%2,%3}, [%4];" \
        : "=r"(r0),"=r"(r1),"=r"(r2),"=r"(r3) : "r"(a))

#define HMMA16816(d, a, b) \
    asm volatile("mma.sync.aligned.m16n8k16.row.col.f32.f16.f16.f32 " \
        "{%0,%1,%2,%3},{%4,%5,%6,%7},{%8,%9},{%0,%1,%2,%3};" \
        : "+f"((d)[0]),"+f"((d)[1]),"+f"((d)[2]),"+f"((d)[3]) \
        : "r"((a)[0]),"r"((a)[1]),"r"((a)[2]),"r"((a)[3]),"r"((b)[0]),"r"((b)[1]))

// ---------------- weight transpose: in[K][N] fp32 -> out[N][K] fp16 ----------------
__global__ void __launch_bounds__(256) wt_kernel(const float* __restrict__ in,
                                                 __half* __restrict__ out, int K, int N)
{
    __shared__ float tile[32][33];
    int bx = blockIdx.x * 32, by = blockIdx.y * 32;
    int x = threadIdx.x & 31, y = threadIdx.x >> 5;
    #pragma unroll
    for (int i = 0; i < 32; i += 8)
        tile[y + i][x] = in[(size_t)(by + y + i) * N + bx + x];
    __syncthreads();
    #pragma unroll
    for (int i = 0; i < 32; i += 8)
        out[(size_t)(bx + y + i) * K + by + x] = __float2half(tile[x][y + i]);
}

// ---------------- CPE gather + residual ----------------
__global__ void __launch_bounds__(256) cpe_kernel(
    const float* __restrict__ data, const float* __restrict__ rt,
    const int* __restrict__ neighbors, const float* __restrict__ cpe_w,
    const float* __restrict__ cpe_scale, const float* __restrict__ cpe_bias)
{
    int bid = blockIdx.x;
    int c = threadIdx.x;
    if (bid >= NPTS) {
        int m = bid - NPTS;
        g_xbuf[((size_t)m * TOK) * CCH + c] = rt[(size_t)m * CCH + c];
        return;
    }
    __shared__ int nb[NEIGH];
    if (threadIdx.x < NEIGH) nb[threadIdx.x] = neighbors[(size_t)bid * NEIGH + threadIdx.x];
    __syncthreads();
    float acc = 0.f;
    #pragma unroll
    for (int j = 0; j < NEIGH; j++)
        acc += data[(size_t)nb[j] * CCH + c] * cpe_w[j * CCH + c];
    float v = data[(size_t)bid * CCH + c] + acc * cpe_scale[c] + cpe_bias[c];
    int m = bid >> 5, k = bid & 31;
    g_xbuf[((size_t)m * TOK + 1 + k) * CCH + c] = v;
}

// ---------------- layernorm: fp32 in -> fp16 out ----------------
__global__ void __launch_bounds__(256) ln_kernel(
    const float* __restrict__ in, __half* __restrict__ out,
    const float* __restrict__ gam, const float* __restrict__ bet)
{
    int warp = threadIdx.x >> 5, lane = threadIdx.x & 31;
    size_t row = (size_t)blockIdx.x * 8 + warp;
    const float* r = in + row * CCH;
    float v[8];
    float s = 0.f;
    #pragma unroll
    for (int i = 0; i < 8; i++) { v[i] = r[lane + i * 32]; s += v[i]; }
    #pragma unroll
    for (int o = 16; o; o >>= 1) s += __shfl_xor_sync(0xffffffffu, s, o);
    float mean = s * (1.f / 256.f);
    float vs = 0.f;
    #pragma unroll
    for (int i = 0; i < 8; i++) { float d = v[i] - mean; vs += d * d; }
    #pragma unroll
    for (int o = 16; o; o >>= 1) vs += __shfl_xor_sync(0xffffffffu, vs, o);
    float rstd = rsqrtf(vs * (1.f / 256.f) + 1e-5f);
    __half* w = out + row * CCH;
    #pragma unroll
    for (int i = 0; i < 8; i++) {
        int c = lane + i * 32;
        w[c] = __float2half((v[i] - mean) * rstd * gam[c] + bet[c]);
    }
}

// ---------------- fp16 tensor-core GEMM (mma.sync m16n8k16) ----------------
// C[rows x N] = A[rows x K] @ Bt[N x K]^T
// 128x128x32 CTA tile, 256 threads (8 warps 2x4), warp tile 64x32.
// MODE 0: half out = A@B+bias       MODE 1: float out = res + A@B+bias
// MODE 2: half out = gelu(A@B+bias) MODE 3: float out = res + A@B+bias, scattered
#define TILE_B   10240            // 128 rows * 80 bytes
#define GEMM_SMEM (4 * TILE_B)    // 40960

template<int MODE, typename OutT>
__global__ void __launch_bounds__(256) hgemm(
    const __half* __restrict__ A, const __half* __restrict__ Bt,
    const float* __restrict__ bias, OutT* __restrict__ Cout,
    const float* __restrict__ res, int Kdim, int Ndim)
{
    extern __shared__ char smraw[];
    uint32_t base = smem_u32(smraw);

    int tid = threadIdx.x;
    int warp = tid >> 5, lane = tid & 31;
    int wm = (warp >> 2) * 64;   // warp row offset
    int wn = (warp & 3) * 32;    // warp col offset
    int la = lane & 7, grp = lane >> 3;
    int g = lane >> 2, t = lane & 3;

    size_t rowBase = (size_t)blockIdx.y * 128;
    int colBase = blockIdx.x * 128;

    const __half* Ag = A  + rowBase * Kdim;
    const __half* Bg = Bt + (size_t)colBase * Kdim;

    // ldmatrix address bases (row stride 80B, conflict-free)
    int aRow = la + (grp & 1) * 8;
    int aKof = (grp >> 1) * 8;        // halves
    int bRow = la + (grp >> 1) * 8;
    int bKof = (grp & 1) * 8;

    float acc[4][4][4];
    #pragma unroll
    for (int mt = 0; mt < 4; mt++)
        #pragma unroll
        for (int nt = 0; nt < 4; nt++)
            #pragma unroll
            for (int i = 0; i < 4; i++) acc[mt][nt][i] = 0.f;

    auto loadStage = [&](int s, int k0) {
        #pragma unroll
        for (int i = 0; i < 2; i++) {
            int idx = i * 256 + tid;
            int row = idx >> 2, c = idx & 3;
            CP_ASYNC16(base + s * TILE_B + row * 80 + c * 16,
                       Ag + (size_t)row * Kdim + k0 + c * 8);
            CP_ASYNC16(base + 2 * TILE_B + s * TILE_B + row * 80 + c * 16,
                       Bg + (size_t)row * Kdim + k0 + c * 8);
        }
    };

    int KT = Kdim >> 5;
    loadStage(0, 0);
    CP_COMMIT();

    for (int kt = 0; kt < KT; kt++) {
        int buf = kt & 1;
        if (kt + 1 < KT) {
            loadStage(buf ^ 1, (kt + 1) << 5);
            CP_COMMIT();
            CP_WAIT(1);
        } else {
            CP_WAIT(0);
        }
        __syncthreads();

        uint32_t aBase = base + buf * TILE_B;
        uint32_t bBase = base + (2 + buf) * TILE_B;

        #pragma unroll
        for (int kk = 0; kk < 2; kk++) {
            int kb = kk * 16;   // halves
            uint32_t af[4][4], bf[4][2];
            #pragma unroll
            for (int mt = 0; mt < 4; mt++) {
                uint32_t ad = aBase + (uint32_t)(wm + mt * 16 + aRow) * 80
                            + (uint32_t)(kb + aKof) * 2;
                LDSM_X4(af[mt][0], af[mt][1], af[mt][2], af[mt][3], ad);
            }
            #pragma unroll
            for (int np = 0; np < 2; np++) {
                uint32_t bd = bBase + (uint32_t)(wn + np * 16 + bRow) * 80
                            + (uint32_t)(kb + bKof) * 2;
                LDSM_X4(bf[2*np][0], bf[2*np][1], bf[2*np+1][0], bf[2*np+1][1], bd);
            }
            #pragma unroll
            for (int mt = 0; mt < 4; mt++)
                #pragma unroll
                for (int nt = 0; nt < 4; nt++)
                    HMMA16816(acc[mt][nt], af[mt], bf[nt]);
        }
        __syncthreads();
    }

    // epilogue: c0:(g,2t) c1:(g,2t+1) c2:(g+8,2t) c3:(g+8,2t+1)
    #pragma unroll
    for (int mt = 0; mt < 4; mt++) {
        #pragma unroll
        for (int nt = 0; nt < 4; nt++) {
            #pragma unroll
            for (int i = 0; i < 4; i++) {
                size_t row = rowBase + wm + mt * 16 + g + (i >> 1) * 8;
                int col = colBase + wn + nt * 8 + 2 * t + (i & 1);
                float v = acc[mt][nt][i] + bias[col];
                if (MODE == 0) {
                    ((__half*)Cout)[row * Ndim + col] = __float2half(v);
                } else if (MODE == 1) {
                    v += res[row * Ndim + col];
                    ((float*)Cout)[row * Ndim + col] = v;
                } else if (MODE == 2) {
                    v = 0.5f * v * (1.0f + erff(v * 0.70710678118654752f));
                    ((__half*)Cout)[row * Ndim + col] = __float2half(v);
                } else {
                    v += res[row * CCH + col];
                    size_t m = row / TOK;
                    int tt = (int)(row - m * TOK);
                    if (tt == 0)
                        ((float*)Cout)[(size_t)NPTS * CCH + m * CCH + col] = v;
                    else
                        ((float*)Cout)[(m * KTOK + (size_t)(tt - 1)) * CCH + col] = v;
                }
            }
        }
    }
}

// ---------------- fused per-window attention (half in, half out) ----------------
#define ATTN_SMEM ((TOK * C3 + HEADS * TOK * TOK + 3 * RPE_NUM * HEADS) * 4)

__global__ void __launch_bounds__(256) attn_kernel(
    const __half* __restrict__ qkv, const int* __restrict__ rel_pos,
    const float* __restrict__ mask, const float* __restrict__ rpe_table,
    __half* __restrict__ outbuf)
{
    extern __shared__ float sm[];
    float* sqkv   = sm;                          // 33*768 fp32
    float* sscore = sm + TOK * C3;               // 8*33*33
    float* stab   = sscore + HEADS * TOK * TOK;  // 153*8

    int m = blockIdx.x, tid = threadIdx.x;
    const __half2* src = (const __half2*)(qkv + (size_t)m * TOK * C3);
    for (int i = tid; i < TOK * C3 / 2; i += 256) {
        float2 f = __half22float2(src[i]);
        sqkv[2 * i] = f.x; sqkv[2 * i + 1] = f.y;
    }
    for (int i = tid; i < 3 * RPE_NUM * HEADS; i += 256) stab[i] = rpe_table[i];
    __syncthreads();

    const float scale = 0.17677669529663687f;

    for (int idx = tid; idx < HEADS * TOK * TOK; idx += 256) {
        int j = idx % TOK;
        int ih = idx / TOK;
        int i = ih % TOK;
        int h = ih / TOK;
        const float* qp = sqkv + i * C3 + h * HDIM;
        const float* kp = sqkv + j * C3 + CCH + h * HDIM;
        float s = 0.f;
        #pragma unroll
        for (int d = 0; d < HDIM; d++) s += qp[d] * kp[d];
        s *= scale;
        if (i > 0 && j > 0) {
            const int* rp = rel_pos + (((size_t)m * KTOK + (i - 1)) * KTOK + (j - 1)) * 3;
            #pragma unroll
            for (int dd = 0; dd < 3; dd++) {
                int r = rp[dd];
                r = min(max(r, -POS_BND), POS_BND);
                s += stab[(r + POS_BND + dd * RPE_NUM) * HEADS + h];
            }
        }
        s += mask[((size_t)m * TOK + i) * TOK + j];
        sscore[(h * TOK + i) * TOK + j] = s;
    }
    __syncthreads();

    int lane = tid & 31, warp = tid >> 5;
    for (int r = warp; r < HEADS * TOK; r += 8) {
        float* rowp = sscore + r * TOK;
        float x0 = rowp[lane];
        float x1 = (lane == 0) ? rowp[32] : -1e30f;
        float mx = fmaxf(x0, x1);
        #pragma unroll
        for (int o = 16; o; o >>= 1) mx = fmaxf(mx, __shfl_xor_sync(0xffffffffu, mx, o));
        float e0 = __expf(x0 - mx);
        float e1 = (lane == 0) ? __expf(x1 - mx) : 0.f;
        float s = e0 + e1;
        #pragma unroll
        for (int o = 16; o; o >>= 1) s += __shfl_xor_sync(0xffffffffu, s, o);
        float inv = 1.f / s;
        rowp[lane] = e0 * inv;
        if (lane == 0) rowp[32] = e1 * inv;
    }
    __syncthreads();

    int h = tid >> 5, d = tid & 31;
    const float* vbase = sqkv + 2 * CCH + h * HDIM + d;
    __half* ob = outbuf + ((size_t)m * TOK) * CCH + h * HDIM + d;
    for (int i = 0; i < TOK; i++) {
        const float* srow = sscore + (h * TOK + i) * TOK;
        float acc = 0.f;
        #pragma unroll
        for (int j = 0; j < TOK; j++) acc += srow[j] * vbase[(size_t)j * C3];
        ob[(size_t)i * CCH] = __float2half(acc);
    }
}

// ---------------- host launcher ----------------
extern "C" void kernel_launch(void* const* d_in, const int* in_sizes, int n_in,
                              void* d_out, int out_size)
{
    const float* data      = (const float*)d_in[0];
    const float* rt        = (const float*)d_in[1];
    const int*   neighbors = (const int*)  d_in[2];
    const int*   rel_pos   = (const int*)  d_in[3];
    const float* mask      = (const float*)d_in[4];
    const float* cpe_w     = (const float*)d_in[5];
    const float* cpe_scale = (const float*)d_in[6];
    const float* cpe_bias  = (const float*)d_in[7];
    const float* ln1_g     = (const float*)d_in[8];
    const float* ln1_b     = (const float*)d_in[9];
    const float* qkv_w     = (const float*)d_in[10];
    const float* qkv_b     = (const float*)d_in[11];
    const float* rpe_table = (const float*)d_in[12];
    const float* proj_w    = (const float*)d_in[13];
    const float* proj_b    = (const float*)d_in[14];
    const float* ln2_g     = (const float*)d_in[15];
    const float* ln2_b     = (const float*)d_in[16];
    const float* mlp_w1    = (const float*)d_in[17];
    const float* mlp_b1    = (const float*)d_in[18];
    const float* mlp_w2    = (const float*)d_in[19];
    const float* mlp_b2    = (const float*)d_in[20];
    float* out = (float*)d_out;

    float*  xbuf;  cudaGetSymbolAddress((void**)&xbuf,  g_xbuf);
    __half* hbuf;  cudaGetSymbolAddress((void**)&hbuf,  g_hbuf16);
    __half* big;   cudaGetSymbolAddress((void**)&big,   g_big16);
    __half* wT;    cudaGetSymbolAddress((void**)&wT,    g_wT16);

    __half* qkvT  = wT;                         // [768][256]
    __half* projT = qkvT + 768 * 256;           // [256][256]
    __half* mlp1T = projT + 256 * 256;          // [1024][256]
    __half* mlp2T = mlp1T + 1024 * 256;         // [256][1024]

    cudaFuncSetAttribute(attn_kernel, cudaFuncAttributeMaxDynamicSharedMemorySize, ATTN_SMEM);

    // 0. transpose + fp16-convert weights
    wt_kernel<<<dim3(768/32, 256/32),  256>>>(qkv_w,  qkvT,  256, 768);
    wt_kernel<<<dim3(256/32, 256/32),  256>>>(proj_w, projT, 256, 256);
    wt_kernel<<<dim3(1024/32, 256/32), 256>>>(mlp_w1, mlp1T, 256, 1024);
    wt_kernel<<<dim3(256/32, 1024/32), 256>>>(mlp_w2, mlp2T, 1024, 256);

    // 1. CPE + residual -> x
    cpe_kernel<<<NPTS + MWIN, 256>>>(data, rt, neighbors, cpe_w, cpe_scale, cpe_bias);

    // 2. LN1 -> fp16
    ln_kernel<<<ROWS / 8, 256>>>(xbuf, hbuf, ln1_g, ln1_b);

    // 3. QKV (fp16 out)
    hgemm<0, __half><<<dim3(C3/128, ROWS/128), 256, GEMM_SMEM>>>(
        hbuf, qkvT, qkv_b, big, nullptr, CCH, C3);

    // 4. attention -> fp16
    attn_kernel<<<MWIN, 256, ATTN_SMEM>>>(big, rel_pos, mask, rpe_table, hbuf);

    // 5. x += attnout @ proj (fp32 residual)
    hgemm<1, float><<<dim3(CCH/128, ROWS/128), 256, GEMM_SMEM>>>(
        hbuf, projT, proj_b, xbuf, xbuf, CCH, CCH);

    // 6. LN2 -> fp16
    ln_kernel<<<ROWS / 8, 256>>>(xbuf, hbuf, ln2_g, ln2_b);

    // 7. hidden = gelu(h @ mlp_w1) (fp16 out)
    hgemm<2, __half><<<dim3(HID/128, ROWS/128), 256, GEMM_SMEM>>>(
        hbuf, mlp1T, mlp_b1, big, nullptr, CCH, HID);

    // 8. out = x + hidden @ mlp_w2 (scattered, fp32)
    hgemm<3, float><<<dim3(CCH/128, ROWS/128), 256, GEMM_SMEM>>>(
        big, mlp2T, mlp_b2, out, xbuf, HID, CCH);
}

// round 5
// speedup vs baseline: 3.1995x; 1.5141x over previous
#include <cuda_runtime.h>
#include <cuda_fp16.h>
#include <math.h>
#include <stdint.h>

// ---------------- problem constants ----------------
#define MWIN   8192
#define KTOK   32
#define TOK    33          // K + G
#define CCH    256
#define HEADS  8
#define HDIM   32
#define NPTS   (MWIN * KTOK)        // 262144
#define ROWS   (MWIN * TOK)         // 270336
#define HID    1024
#define NEIGH  27
#define POS_BND 25
#define RPE_NUM 51
#define C3     768

// ---------------- scratch ----------------
__device__ float  g_xbuf [(size_t)ROWS * CCH];   // residual stream (fp32)
__device__ __half g_hbuf16[(size_t)ROWS * CCH];  // LN out / attn out (fp16)
__device__ __half g_big16 [(size_t)ROWS * HID];  // qkv / mlp hidden (fp16)
__device__ __half g_wT16  [768*256 + 256*256 + 1024*256 + 256*1024]; // W^T fp16

// ---------------- PTX helpers ----------------
__device__ __forceinline__ uint32_t smem_u32(const void* p) {
    uint32_t a;
    asm("{ .reg .u64 t; cvta.to.shared.u64 t, %1; cvt.u32.u64 %0, t; }" : "=r"(a) : "l"(p));
    return a;
}
#define CP_ASYNC16(dst_u32, src_ptr) \
    asm volatile("cp.async.cg.shared.global [%0], [%1], 16;\n" :: "r"(dst_u32), "l"(src_ptr))
#define CP_COMMIT() asm volatile("cp.async.commit_group;\n")
#define CP_WAIT(n)  asm volatile("cp.async.wait_group %0;\n" :: "n"(n))

#define LDSM_X4(r0,r1,r2,r3,a) \
    asm volatile("ldmatrix.sync.aligned.m8n8.x4.shared.b16 {%0,%1,%2,%3}, [%4];" \
        : "=r"(r0),"=r"(r1),"=r"(r2),"=r"(r3) : "r"(a))

#define HMMA16816(d, a, b) \
    asm volatile("mma.sync.aligned.m16n8k16.row.col.f32.f16.f16.f32 " \
        "{%0,%1,%2,%3},{%4,%5,%6,%7},{%8,%9},{%0,%1,%2,%3};" \
        : "+f"((d)[0]),"+f"((d)[1]),"+f"((d)[2]),"+f"((d)[3]) \
        : "r"((a)[0]),"r"((a)[1]),"r"((a)[2]),"r"((a)[3]),"r"((b)[0]),"r"((b)[1]))

// ---------------- weight transpose: in[K][N] fp32 -> out[N][K] fp16 ----------------
__global__ void __launch_bounds__(256) wt_kernel(const float* __restrict__ in,
                                                 __half* __restrict__ out, int K, int N)
{
    __shared__ float tile[32][33];
    int bx = blockIdx.x * 32, by = blockIdx.y * 32;
    int x = threadIdx.x & 31, y = threadIdx.x >> 5;
    #pragma unroll
    for (int i = 0; i < 32; i += 8)
        tile[y + i][x] = in[(size_t)(by + y + i) * N + bx + x];
    __syncthreads();
    #pragma unroll
    for (int i = 0; i < 32; i += 8)
        out[(size_t)(bx + y + i) * K + by + x] = __float2half(tile[x][y + i]);
}

// ---------------- CPE gather + residual ----------------
__global__ void __launch_bounds__(256) cpe_kernel(
    const float* __restrict__ data, const float* __restrict__ rt,
    const int* __restrict__ neighbors, const float* __restrict__ cpe_w,
    const float* __restrict__ cpe_scale, const float* __restrict__ cpe_bias)
{
    int bid = blockIdx.x;
    int c = threadIdx.x;
    if (bid >= NPTS) {
        int m = bid - NPTS;
        g_xbuf[((size_t)m * TOK) * CCH + c] = rt[(size_t)m * CCH + c];
        return;
    }
    __shared__ int nb[NEIGH];
    if (threadIdx.x < NEIGH) nb[threadIdx.x] = neighbors[(size_t)bid * NEIGH + threadIdx.x];
    __syncthreads();
    float acc = 0.f;
    #pragma unroll
    for (int j = 0; j < NEIGH; j++)
        acc += data[(size_t)nb[j] * CCH + c] * cpe_w[j * CCH + c];
    float v = data[(size_t)bid * CCH + c] + acc * cpe_scale[c] + cpe_bias[c];
    int m = bid >> 5, k = bid & 31;
    g_xbuf[((size_t)m * TOK + 1 + k) * CCH + c] = v;
}

// ---------------- layernorm: fp32 in -> fp16 out ----------------
__global__ void __launch_bounds__(256) ln_kernel(
    const float* __restrict__ in, __half* __restrict__ out,
    const float* __restrict__ gam, const float* __restrict__ bet)
{
    int warp = threadIdx.x >> 5, lane = threadIdx.x & 31;
    size_t row = (size_t)blockIdx.x * 8 + warp;
    const float* r = in + row * CCH;
    float v[8];
    float s = 0.f;
    #pragma unroll
    for (int i = 0; i < 8; i++) { v[i] = r[lane + i * 32]; s += v[i]; }
    #pragma unroll
    for (int o = 16; o; o >>= 1) s += __shfl_xor_sync(0xffffffffu, s, o);
    float mean = s * (1.f / 256.f);
    float vs = 0.f;
    #pragma unroll
    for (int i = 0; i < 8; i++) { float d = v[i] - mean; vs += d * d; }
    #pragma unroll
    for (int o = 16; o; o >>= 1) vs += __shfl_xor_sync(0xffffffffu, vs, o);
    float rstd = rsqrtf(vs * (1.f / 256.f) + 1e-5f);
    __half* w = out + row * CCH;
    #pragma unroll
    for (int i = 0; i < 8; i++) {
        int c = lane + i * 32;
        w[c] = __float2half((v[i] - mean) * rstd * gam[c] + bet[c]);
    }
}

// ---------------- fp16 tensor-core GEMM (mma.sync m16n8k16), 3-stage pipeline ----------------
// C[rows x N] = A[rows x K] @ Bt[N x K]^T
// 128x128x32 CTA tile, 256 threads (8 warps 2x4), warp tile 64x32.
#define TILE_B   10240            // 128 rows * 80 bytes
#define GEMM_SMEM (6 * TILE_B)    // 61440 (3 stages x (A,B))

template<int MODE, typename OutT>
__global__ void __launch_bounds__(256) hgemm(
    const __half* __restrict__ A, const __half* __restrict__ Bt,
    const float* __restrict__ bias, OutT* __restrict__ Cout,
    const float* __restrict__ res, int Kdim, int Ndim)
{
    extern __shared__ char smraw[];
    uint32_t base = smem_u32(smraw);

    int tid = threadIdx.x;
    int warp = tid >> 5, lane = tid & 31;
    int wm = (warp >> 2) * 64;
    int wn = (warp & 3) * 32;
    int la = lane & 7, grp = lane >> 3;
    int g = lane >> 2, t = lane & 3;

    size_t rowBase = (size_t)blockIdx.y * 128;
    int colBase = blockIdx.x * 128;

    const __half* Ag = A  + rowBase * Kdim;
    const __half* Bg = Bt + (size_t)colBase * Kdim;

    int aRow = la + (grp & 1) * 8;
    int aKof = (grp >> 1) * 8;
    int bRow = la + (grp >> 1) * 8;
    int bKof = (grp & 1) * 8;

    float acc[4][4][4];
    #pragma unroll
    for (int mt = 0; mt < 4; mt++)
        #pragma unroll
        for (int nt = 0; nt < 4; nt++)
            #pragma unroll
            for (int i = 0; i < 4; i++) acc[mt][nt][i] = 0.f;

    auto loadStage = [&](int s, int k0) {
        #pragma unroll
        for (int i = 0; i < 2; i++) {
            int idx = i * 256 + tid;
            int row = idx >> 2, c = idx & 3;
            CP_ASYNC16(base + s * TILE_B + row * 80 + c * 16,
                       Ag + (size_t)row * Kdim + k0 + c * 8);
            CP_ASYNC16(base + (3 + s) * TILE_B + row * 80 + c * 16,
                       Bg + (size_t)row * Kdim + k0 + c * 8);
        }
    };

    int KT = Kdim >> 5;
    loadStage(0, 0);  CP_COMMIT();
    loadStage(1, 32); CP_COMMIT();

    for (int kt = 0; kt < KT; kt++) {
        if (kt + 1 < KT) CP_WAIT(1); else CP_WAIT(0);
        __syncthreads();
        if (kt + 2 < KT) { loadStage((kt + 2) % 3, (kt + 2) << 5); CP_COMMIT(); }

        int buf = kt % 3;
        uint32_t aBase = base + buf * TILE_B;
        uint32_t bBase = base + (3 + buf) * TILE_B;

        #pragma unroll
        for (int kk = 0; kk < 2; kk++) {
            int kb = kk * 16;
            uint32_t af[4][4], bf[4][2];
            #pragma unroll
            for (int mt = 0; mt < 4; mt++) {
                uint32_t ad = aBase + (uint32_t)(wm + mt * 16 + aRow) * 80
                            + (uint32_t)(kb + aKof) * 2;
                LDSM_X4(af[mt][0], af[mt][1], af[mt][2], af[mt][3], ad);
            }
            #pragma unroll
            for (int np = 0; np < 2; np++) {
                uint32_t bd = bBase + (uint32_t)(wn + np * 16 + bRow) * 80
                            + (uint32_t)(kb + bKof) * 2;
                LDSM_X4(bf[2*np][0], bf[2*np][1], bf[2*np+1][0], bf[2*np+1][1], bd);
            }
            #pragma unroll
            for (int mt = 0; mt < 4; mt++)
                #pragma unroll
                for (int nt = 0; nt < 4; nt++)
                    HMMA16816(acc[mt][nt], af[mt], bf[nt]);
        }
    }

    // epilogue: pairs (2t,2t+1) are consecutive cols -> vector stores
    #pragma unroll
    for (int mt = 0; mt < 4; mt++) {
        #pragma unroll
        for (int nt = 0; nt < 4; nt++) {
            int col = colBase + wn + nt * 8 + 2 * t;
            float b0 = bias[col], b1 = bias[col + 1];
            #pragma unroll
            for (int hf = 0; hf < 2; hf++) {
                size_t row = rowBase + wm + mt * 16 + g + hf * 8;
                float v0 = acc[mt][nt][hf * 2 + 0] + b0;
                float v1 = acc[mt][nt][hf * 2 + 1] + b1;
                if (MODE == 0) {
                    *(__half2*)&((__half*)Cout)[row * Ndim + col] =
                        __floats2half2_rn(v0, v1);
                } else if (MODE == 1) {
                    const float2 r2 = *(const float2*)&res[row * Ndim + col];
                    *(float2*)&((float*)Cout)[row * Ndim + col] =
                        make_float2(v0 + r2.x, v1 + r2.y);
                } else if (MODE == 2) {
                    v0 = 0.5f * v0 * (1.0f + erff(v0 * 0.70710678118654752f));
                    v1 = 0.5f * v1 * (1.0f + erff(v1 * 0.70710678118654752f));
                    *(__half2*)&((__half*)Cout)[row * Ndim + col] =
                        __floats2half2_rn(v0, v1);
                } else {
                    const float2 r2 = *(const float2*)&res[row * CCH + col];
                    size_t m = row / TOK;
                    int tt = (int)(row - m * TOK);
                    float* dst = (tt == 0)
                        ? ((float*)Cout + (size_t)NPTS * CCH + m * CCH + col)
                        : ((float*)Cout + (m * KTOK + (size_t)(tt - 1)) * CCH + col);
                    *(float2*)dst = make_float2(v0 + r2.x, v1 + r2.y);
                }
            }
        }
    }
}

// ---------------- fused per-window attention (conflict-free K-transpose) ----------------
// smem floats: sq 33*768 | KT 256*33 | scores 8*33*33 | rpe 153*8
#define ATTN_THREADS 512
#define SQ_F   (TOK * C3)                 // 25344
#define KT_F   (CCH * TOK)                // 8448
#define SC_F   (HEADS * TOK * TOK)        // 8712
#define TAB_F  (3 * RPE_NUM * HEADS)      // 1224
#define ATTN_SMEM ((SQ_F + KT_F + SC_F + TAB_F) * 4)

__global__ void __launch_bounds__(ATTN_THREADS) attn_kernel(
    const __half* __restrict__ qkv, const int* __restrict__ rel_pos,
    const float* __restrict__ mask, const float* __restrict__ rpe_table,
    __half* __restrict__ outbuf)
{
    extern __shared__ float sm[];
    float* sq     = sm;
    float* ktb    = sm + SQ_F;
    float* sscore = ktb + KT_F;
    float* stab   = sscore + SC_F;

    int m = blockIdx.x, tid = threadIdx.x;
    const __half2* src = (const __half2*)(qkv + (size_t)m * TOK * C3);
    for (int i = tid; i < SQ_F / 2; i += ATTN_THREADS) {
        float2 f = __half22float2(src[i]);
        sq[2 * i] = f.x; sq[2 * i + 1] = f.y;
    }
    for (int i = tid; i < TAB_F; i += ATTN_THREADS) stab[i] = rpe_table[i];
    __syncthreads();

    // transpose K into ktb[c][j]  (stride 33 -> conflict-free both ways)
    for (int idx = tid; idx < KT_F; idx += ATTN_THREADS) {
        int c = idx & 255, j = idx >> 8;
        ktb[c * TOK + j] = sq[j * C3 + CCH + c];
    }
    __syncthreads();

    const float scale = 0.17677669529663687f;

    for (int idx = tid; idx < SC_F; idx += ATTN_THREADS) {
        int j = idx % TOK;
        int ih = idx / TOK;
        int i = ih % TOK;
        int h = ih / TOK;
        const float* qp = sq + i * C3 + h * HDIM;
        const float* kp = ktb + h * HDIM * TOK + j;
        float s = 0.f;
        #pragma unroll
        for (int d = 0; d < HDIM; d++) s += qp[d] * kp[d * TOK];
        s *= scale;
        if (i > 0 && j > 0) {
            const int* rp = rel_pos + (((size_t)m * KTOK + (i - 1)) * KTOK + (j - 1)) * 3;
            #pragma unroll
            for (int dd = 0; dd < 3; dd++) {
                int r = rp[dd];
                r = min(max(r, -POS_BND), POS_BND);
                s += stab[(r + POS_BND + dd * RPE_NUM) * HEADS + h];
            }
        }
        s += mask[((size_t)m * TOK + i) * TOK + j];
        sscore[(h * TOK + i) * TOK + j] = s;
    }
    __syncthreads();

    int lane = tid & 31, warp = tid >> 5;   // 16 warps
    for (int r = warp; r < HEADS * TOK; r += 16) {
        float* rowp = sscore + r * TOK;
        float x0 = rowp[lane];
        float x1 = (lane == 0) ? rowp[32] : -1e30f;
        float mx = fmaxf(x0, x1);
        #pragma unroll
        for (int o = 16; o; o >>= 1) mx = fmaxf(mx, __shfl_xor_sync(0xffffffffu, mx, o));
        float e0 = __expf(x0 - mx);
        float e1 = (lane == 0) ? __expf(x1 - mx) : 0.f;
        float s = e0 + e1;
        #pragma unroll
        for (int o = 16; o; o >>= 1) s += __shfl_xor_sync(0xffffffffu, s, o);
        float inv = 1.f / s;
        rowp[lane] = e0 * inv;
        if (lane == 0) rowp[32] = e1 * inv;
    }
    __syncthreads();

    // AV: 512 threads: h=(tid>>5)&7, d=lane, i strided by pair
    int h = (tid >> 5) & 7, d = lane, pair = tid >> 8;
    const float* vbase = sq + 2 * CCH + h * HDIM + d;
    __half* ob = outbuf + ((size_t)m * TOK) * CCH + h * HDIM + d;
    for (int i = pair; i < TOK; i += 2) {
        const float* srow = sscore + (h * TOK + i) * TOK;
        float acc = 0.f;
        #pragma unroll
        for (int j = 0; j < TOK; j++) acc += srow[j] * vbase[(size_t)j * C3];
        ob[(size_t)i * CCH] = __float2half(acc);
    }
}

// ---------------- host launcher ----------------
extern "C" void kernel_launch(void* const* d_in, const int* in_sizes, int n_in,
                              void* d_out, int out_size)
{
    const float* data      = (const float*)d_in[0];
    const float* rt        = (const float*)d_in[1];
    const int*   neighbors = (const int*)  d_in[2];
    const int*   rel_pos   = (const int*)  d_in[3];
    const float* mask      = (const float*)d_in[4];
    const float* cpe_w     = (const float*)d_in[5];
    const float* cpe_scale = (const float*)d_in[6];
    const float* cpe_bias  = (const float*)d_in[7];
    const float* ln1_g     = (const float*)d_in[8];
    const float* ln1_b     = (const float*)d_in[9];
    const float* qkv_w     = (const float*)d_in[10];
    const float* qkv_b     = (const float*)d_in[11];
    const float* rpe_table = (const float*)d_in[12];
    const float* proj_w    = (const float*)d_in[13];
    const float* proj_b    = (const float*)d_in[14];
    const float* ln2_g     = (const float*)d_in[15];
    const float* ln2_b     = (const float*)d_in[16];
    const float* mlp_w1    = (const float*)d_in[17];
    const float* mlp_b1    = (const float*)d_in[18];
    const float* mlp_w2    = (const float*)d_in[19];
    const float* mlp_b2    = (const float*)d_in[20];
    float* out = (float*)d_out;

    float*  xbuf;  cudaGetSymbolAddress((void**)&xbuf,  g_xbuf);
    __half* hbuf;  cudaGetSymbolAddress((void**)&hbuf,  g_hbuf16);
    __half* big;   cudaGetSymbolAddress((void**)&big,   g_big16);
    __half* wT;    cudaGetSymbolAddress((void**)&wT,    g_wT16);

    __half* qkvT  = wT;
    __half* projT = qkvT + 768 * 256;
    __half* mlp1T = projT + 256 * 256;
    __half* mlp2T = mlp1T + 1024 * 256;

    cudaFuncSetAttribute(attn_kernel, cudaFuncAttributeMaxDynamicSharedMemorySize, ATTN_SMEM);
    cudaFuncSetAttribute(hgemm<0, __half>, cudaFuncAttributeMaxDynamicSharedMemorySize, GEMM_SMEM);
    cudaFuncSetAttribute(hgemm<1, float>,  cudaFuncAttributeMaxDynamicSharedMemorySize, GEMM_SMEM);
    cudaFuncSetAttribute(hgemm<2, __half>, cudaFuncAttributeMaxDynamicSharedMemorySize, GEMM_SMEM);
    cudaFuncSetAttribute(hgemm<3, float>,  cudaFuncAttributeMaxDynamicSharedMemorySize, GEMM_SMEM);

    // 0. transpose + fp16-convert weights
    wt_kernel<<<dim3(768/32, 256/32),  256>>>(qkv_w,  qkvT,  256, 768);
    wt_kernel<<<dim3(256/32, 256/32),  256>>>(proj_w, projT, 256, 256);
    wt_kernel<<<dim3(1024/32, 256/32), 256>>>(mlp_w1, mlp1T, 256, 1024);
    wt_kernel<<<dim3(256/32, 1024/32), 256>>>(mlp_w2, mlp2T, 1024, 256);

    // 1. CPE + residual -> x
    cpe_kernel<<<NPTS + MWIN, 256>>>(data, rt, neighbors, cpe_w, cpe_scale, cpe_bias);

    // 2. LN1 -> fp16
    ln_kernel<<<ROWS / 8, 256>>>(xbuf, hbuf, ln1_g, ln1_b);

    // 3. QKV (fp16 out)
    hgemm<0, __half><<<dim3(C3/128, ROWS/128), 256, GEMM_SMEM>>>(
        hbuf, qkvT, qkv_b, big, nullptr, CCH, C3);

    // 4. attention -> fp16
    attn_kernel<<<MWIN, ATTN_THREADS, ATTN_SMEM>>>(big, rel_pos, mask, rpe_table, hbuf);

    // 5. x += attnout @ proj (fp32 residual)
    hgemm<1, float><<<dim3(CCH/128, ROWS/128), 256, GEMM_SMEM>>>(
        hbuf, projT, proj_b, xbuf, xbuf, CCH, CCH);

    // 6. LN2 -> fp16
    ln_kernel<<<ROWS / 8, 256>>>(xbuf, hbuf, ln2_g, ln2_b);

    // 7. hidden = gelu(h @ mlp_w1) (fp16 out)
    hgemm<2, __half><<<dim3(HID/128, ROWS/128), 256, GEMM_SMEM>>>(
        hbuf, mlp1T, mlp_b1, big, nullptr, CCH, HID);

    // 8. out = x + hidden @ mlp_w2 (scattered, fp32)
    hgemm<3, float><<<dim3(CCH/128, ROWS/128), 256, GEMM_SMEM>>>(
        big, mlp2T, mlp_b2, out, xbuf, HID, CCH);
}

// round 6
// speedup vs baseline: 3.4465x; 1.0772x over previous
#include <cuda_runtime.h>
#include <cuda_fp16.h>
#include <math.h>
#include <stdint.h>

// ---------------- problem constants ----------------
#define MWIN   8192
#define KTOK   32
#define TOK    33          // K + G
#define CCH    256
#define HEADS  8
#define HDIM   32
#define NPTS   (MWIN * KTOK)        // 262144
#define ROWS   (MWIN * TOK)         // 270336
#define HID    1024
#define NEIGH  27
#define POS_BND 25
#define RPE_NUM 51
#define C3     768

// ---------------- scratch ----------------
__device__ float  g_xbuf [(size_t)ROWS * CCH];   // residual stream (fp32)
__device__ __half g_hbuf16[(size_t)ROWS * CCH];  // LN out / attn out (fp16)
__device__ __half g_big16 [(size_t)ROWS * HID];  // qkv / mlp hidden (fp16)
__device__ __half g_wT16  [768*256 + 256*256 + 1024*256 + 256*1024]; // W^T fp16
__device__ __half g_data16[(size_t)NPTS * CCH];  // fp16 mirror of data for gather

// ---------------- PTX helpers ----------------
__device__ __forceinline__ uint32_t smem_u32(const void* p) {
    uint32_t a;
    asm("{ .reg .u64 t; cvta.to.shared.u64 t, %1; cvt.u32.u64 %0, t; }" : "=r"(a) : "l"(p));
    return a;
}
#define CP_ASYNC16(dst_u32, src_ptr) \
    asm volatile("cp.async.cg.shared.global [%0], [%1], 16;\n" :: "r"(dst_u32), "l"(src_ptr))
#define CP_COMMIT() asm volatile("cp.async.commit_group;\n")
#define CP_WAIT(n)  asm volatile("cp.async.wait_group %0;\n" :: "n"(n))

#define LDSM_X4(r0,r1,r2,r3,a) \
    asm volatile("ldmatrix.sync.aligned.m8n8.x4.shared.b16 {%0,%1,%2,%3}, [%4];" \
        : "=r"(r0),"=r"(r1),"=r"(r2),"=r"(r3) : "r"(a))

#define HMMA16816(d, a, b) \
    asm volatile("mma.sync.aligned.m16n8k16.row.col.f32.f16.f16.f32 " \
        "{%0,%1,%2,%3},{%4,%5,%6,%7},{%8,%9},{%0,%1,%2,%3};" \
        : "+f"((d)[0]),"+f"((d)[1]),"+f"((d)[2]),"+f"((d)[3]) \
        : "r"((a)[0]),"r"((a)[1]),"r"((a)[2]),"r"((a)[3]),"r"((b)[0]),"r"((b)[1]))

// ---------------- weight transpose: in[K][N] fp32 -> out[N][K] fp16 ----------------
__global__ void __launch_bounds__(256) wt_kernel(const float* __restrict__ in,
                                                 __half* __restrict__ out, int K, int N)
{
    __shared__ float tile[32][33];
    int bx = blockIdx.x * 32, by = blockIdx.y * 32;
    int x = threadIdx.x & 31, y = threadIdx.x >> 5;
    #pragma unroll
    for (int i = 0; i < 32; i += 8)
        tile[y + i][x] = in[(size_t)(by + y + i) * N + bx + x];
    __syncthreads();
    #pragma unroll
    for (int i = 0; i < 32; i += 8)
        out[(size_t)(bx + y + i) * K + by + x] = __float2half(tile[x][y + i]);
}

// ---------------- data -> fp16 mirror ----------------
__global__ void __launch_bounds__(256) cvt_data_kernel(const float* __restrict__ data)
{
    size_t i = ((size_t)blockIdx.x * 256 + threadIdx.x) * 4;
    float4 f = *(const float4*)(data + i);
    __half2* d = (__half2*)(g_data16 + i);
    d[0] = __floats2half2_rn(f.x, f.y);
    d[1] = __floats2half2_rn(f.z, f.w);
}

// ---------------- CPE gather (fp16 reads) + residual ----------------
__global__ void __launch_bounds__(128) cpe_kernel(
    const float* __restrict__ data, const float* __restrict__ rt,
    const int* __restrict__ neighbors, const float* __restrict__ cpe_w,
    const float* __restrict__ cpe_scale, const float* __restrict__ cpe_bias)
{
    int bid = blockIdx.x;
    int tid = threadIdx.x;
    if (bid >= NPTS) {
        int m = bid - NPTS;
        const float2* s = (const float2*)(rt + (size_t)m * CCH);
        float2* d = (float2*)(g_xbuf + ((size_t)m * TOK) * CCH);
        d[tid] = s[tid];
        return;
    }
    __shared__ int nb[NEIGH];
    if (tid < NEIGH) nb[tid] = neighbors[(size_t)bid * NEIGH + tid];
    __syncthreads();
    int c = tid * 2;
    float ax = 0.f, ay = 0.f;
    #pragma unroll
    for (int j = 0; j < NEIGH; j++) {
        __half2 h = *(const __half2*)(g_data16 + (size_t)nb[j] * CCH + c);
        float2 f = __half22float2(h);
        float2 w = *(const float2*)(cpe_w + j * CCH + c);
        ax += f.x * w.x; ay += f.y * w.y;
    }
    float2 d0 = *(const float2*)(data + (size_t)bid * CCH + c);
    float2 sc = *(const float2*)(cpe_scale + c);
    float2 bi = *(const float2*)(cpe_bias + c);
    int m = bid >> 5, k = bid & 31;
    float2 v = make_float2(d0.x + ax * sc.x + bi.x, d0.y + ay * sc.y + bi.y);
    *(float2*)(g_xbuf + ((size_t)m * TOK + 1 + k) * CCH + c) = v;
}

// ---------------- layernorm: fp32 in -> fp16 out ----------------
__global__ void __launch_bounds__(256) ln_kernel(
    const float* __restrict__ in, __half* __restrict__ out,
    const float* __restrict__ gam, const float* __restrict__ bet)
{
    int warp = threadIdx.x >> 5, lane = threadIdx.x & 31;
    size_t row = (size_t)blockIdx.x * 8 + warp;
    const float* r = in + row * CCH;
    float v[8];
    float s = 0.f;
    #pragma unroll
    for (int i = 0; i < 8; i++) { v[i] = r[lane + i * 32]; s += v[i]; }
    #pragma unroll
    for (int o = 16; o; o >>= 1) s += __shfl_xor_sync(0xffffffffu, s, o);
    float mean = s * (1.f / 256.f);
    float vs = 0.f;
    #pragma unroll
    for (int i = 0; i < 8; i++) { float d = v[i] - mean; vs += d * d; }
    #pragma unroll
    for (int o = 16; o; o >>= 1) vs += __shfl_xor_sync(0xffffffffu, vs, o);
    float rstd = rsqrtf(vs * (1.f / 256.f) + 1e-5f);
    __half* w = out + row * CCH;
    #pragma unroll
    for (int i = 0; i < 8; i++) {
        int c = lane + i * 32;
        w[c] = __float2half((v[i] - mean) * rstd * gam[c] + bet[c]);
    }
}

// ---------------- fp16 tensor-core GEMM: CTA 128x256, warp tile 64x64 ----------------
// C[rows x N] = A[rows x K] @ Bt[N x K]^T ; 256 threads (8 warps 2x4), 3-stage cp.async.
#define A_TILE   10240            // 128 rows * 80 bytes
#define B_TILE   20480            // 256 rows * 80 bytes
#define GEMM_SMEM (3 * (A_TILE + B_TILE))   // 92160

template<int MODE, typename OutT>
__global__ void __launch_bounds__(256) hgemm(
    const __half* __restrict__ A, const __half* __restrict__ Bt,
    const float* __restrict__ bias, OutT* __restrict__ Cout,
    const float* __restrict__ res, int Kdim, int Ndim)
{
    extern __shared__ char smraw[];
    uint32_t base = smem_u32(smraw);

    int tid = threadIdx.x;
    int warp = tid >> 5, lane = tid & 31;
    int wm = (warp >> 2) * 64;    // 0 or 64
    int wn = (warp & 3) * 64;     // 0..192
    int la = lane & 7, grp = lane >> 3;
    int g = lane >> 2, t = lane & 3;

    size_t rowBase = (size_t)blockIdx.y * 128;
    int colBase = blockIdx.x * 256;

    const __half* Ag = A  + rowBase * Kdim;
    const __half* Bg = Bt + (size_t)colBase * Kdim;

    int aRow = la + (grp & 1) * 8;
    int aKof = (grp >> 1) * 8;
    int bRow = la + (grp >> 1) * 8;
    int bKof = (grp & 1) * 8;

    float acc[4][8][4];
    #pragma unroll
    for (int mt = 0; mt < 4; mt++)
        #pragma unroll
        for (int nt = 0; nt < 8; nt++)
            #pragma unroll
            for (int i = 0; i < 4; i++) acc[mt][nt][i] = 0.f;

    auto loadStage = [&](int s, int k0) {
        #pragma unroll
        for (int i = 0; i < 2; i++) {
            int idx = i * 256 + tid;
            int row = idx >> 2, c = idx & 3;
            CP_ASYNC16(base + s * A_TILE + row * 80 + c * 16,
                       Ag + (size_t)row * Kdim + k0 + c * 8);
        }
        #pragma unroll
        for (int i = 0; i < 4; i++) {
            int idx = i * 256 + tid;
            int row = idx >> 2, c = idx & 3;
            CP_ASYNC16(base + 3 * A_TILE + s * B_TILE + row * 80 + c * 16,
                       Bg + (size_t)row * Kdim + k0 + c * 8);
        }
    };

    int KT = Kdim >> 5;
    loadStage(0, 0);  CP_COMMIT();
    loadStage(1, 32); CP_COMMIT();

    for (int kt = 0; kt < KT; kt++) {
        if (kt + 1 < KT) CP_WAIT(1); else CP_WAIT(0);
        __syncthreads();
        if (kt + 2 < KT) { loadStage((kt + 2) % 3, (kt + 2) << 5); CP_COMMIT(); }

        int buf = kt % 3;
        uint32_t aBase = base + buf * A_TILE;
        uint32_t bBase = base + 3 * A_TILE + buf * B_TILE;

        #pragma unroll
        for (int kk = 0; kk < 2; kk++) {
            int kb = kk * 16;
            uint32_t af[4][4], bf[8][2];
            #pragma unroll
            for (int mt = 0; mt < 4; mt++) {
                uint32_t ad = aBase + (uint32_t)(wm + mt * 16 + aRow) * 80
                            + (uint32_t)(kb + aKof) * 2;
                LDSM_X4(af[mt][0], af[mt][1], af[mt][2], af[mt][3], ad);
            }
            #pragma unroll
            for (int np = 0; np < 4; np++) {
                uint32_t bd = bBase + (uint32_t)(wn + np * 16 + bRow) * 80
                            + (uint32_t)(kb + bKof) * 2;
                LDSM_X4(bf[2*np][0], bf[2*np][1], bf[2*np+1][0], bf[2*np+1][1], bd);
            }
            #pragma unroll
            for (int mt = 0; mt < 4; mt++)
                #pragma unroll
                for (int nt = 0; nt < 8; nt++)
                    HMMA16816(acc[mt][nt], af[mt], bf[nt]);
        }
    }

    // epilogue: pairs (2t,2t+1) consecutive cols -> vector stores
    #pragma unroll
    for (int mt = 0; mt < 4; mt++) {
        #pragma unroll
        for (int nt = 0; nt < 8; nt++) {
            int col = colBase + wn + nt * 8 + 2 * t;
            float b0 = bias[col], b1 = bias[col + 1];
            #pragma unroll
            for (int hf = 0; hf < 2; hf++) {
                size_t row = rowBase + wm + mt * 16 + g + hf * 8;
                float v0 = acc[mt][nt][hf * 2 + 0] + b0;
                float v1 = acc[mt][nt][hf * 2 + 1] + b1;
                if (MODE == 0) {
                    *(__half2*)&((__half*)Cout)[row * Ndim + col] =
                        __floats2half2_rn(v0, v1);
                } else if (MODE == 1) {
                    const float2 r2 = *(const float2*)&res[row * Ndim + col];
                    *(float2*)&((float*)Cout)[row * Ndim + col] =
                        make_float2(v0 + r2.x, v1 + r2.y);
                } else if (MODE == 2) {
                    v0 = 0.5f * v0 * (1.0f + erff(v0 * 0.70710678118654752f));
                    v1 = 0.5f * v1 * (1.0f + erff(v1 * 0.70710678118654752f));
                    *(__half2*)&((__half*)Cout)[row * Ndim + col] =
                        __floats2half2_rn(v0, v1);
                } else {
                    const float2 r2 = *(const float2*)&res[row * CCH + col];
                    size_t m = row / TOK;
                    int tt = (int)(row - m * TOK);
                    float* dst = (tt == 0)
                        ? ((float*)Cout + (size_t)NPTS * CCH + m * CCH + col)
                        : ((float*)Cout + (m * KTOK + (size_t)(tt - 1)) * CCH + col);
                    *(float2*)dst = make_float2(v0 + r2.x, v1 + r2.y);
                }
            }
        }
    }
}

// ---------------- fused per-window attention (conflict-free K-transpose) ----------------
#define ATTN_THREADS 512
#define SQ_F   (TOK * C3)                 // 25344
#define KT_F   (CCH * TOK)                // 8448
#define SC_F   (HEADS * TOK * TOK)        // 8712
#define TAB_F  (3 * RPE_NUM * HEADS)      // 1224
#define ATTN_SMEM ((SQ_F + KT_F + SC_F + TAB_F) * 4)

__global__ void __launch_bounds__(ATTN_THREADS) attn_kernel(
    const __half* __restrict__ qkv, const int* __restrict__ rel_pos,
    const float* __restrict__ mask, const float* __restrict__ rpe_table,
    __half* __restrict__ outbuf)
{
    extern __shared__ float sm[];
    float* sq     = sm;
    float* ktb    = sm + SQ_F;
    float* sscore = ktb + KT_F;
    float* stab   = sscore + SC_F;

    int m = blockIdx.x, tid = threadIdx.x;
    const __half2* src = (const __half2*)(qkv + (size_t)m * TOK * C3);
    for (int i = tid; i < SQ_F / 2; i += ATTN_THREADS) {
        float2 f = __half22float2(src[i]);
        sq[2 * i] = f.x; sq[2 * i + 1] = f.y;
    }
    for (int i = tid; i < TAB_F; i += ATTN_THREADS) stab[i] = rpe_table[i];
    __syncthreads();

    for (int idx = tid; idx < KT_F; idx += ATTN_THREADS) {
        int c = idx & 255, j = idx >> 8;
        ktb[c * TOK + j] = sq[j * C3 + CCH + c];
    }
    __syncthreads();

    const float scale = 0.17677669529663687f;

    for (int idx = tid; idx < SC_F; idx += ATTN_THREADS) {
        int j = idx % TOK;
        int ih = idx / TOK;
        int i = ih % TOK;
        int h = ih / TOK;
        const float* qp = sq + i * C3 + h * HDIM;
        const float* kp = ktb + h * HDIM * TOK + j;
        float s = 0.f;
        #pragma unroll
        for (int d = 0; d < HDIM; d++) s += qp[d] * kp[d * TOK];
        s *= scale;
        if (i > 0 && j > 0) {
            const int* rp = rel_pos + (((size_t)m * KTOK + (i - 1)) * KTOK + (j - 1)) * 3;
            #pragma unroll
            for (int dd = 0; dd < 3; dd++) {
                int r = rp[dd];
                r = min(max(r, -POS_BND), POS_BND);
                s += stab[(r + POS_BND + dd * RPE_NUM) * HEADS + h];
            }
        }
        s += mask[((size_t)m * TOK + i) * TOK + j];
        sscore[(h * TOK + i) * TOK + j] = s;
    }
    __syncthreads();

    int lane = tid & 31, warp = tid >> 5;
    for (int r = warp; r < HEADS * TOK; r += 16) {
        float* rowp = sscore + r * TOK;
        float x0 = rowp[lane];
        float x1 = (lane == 0) ? rowp[32] : -1e30f;
        float mx = fmaxf(x0, x1);
        #pragma unroll
        for (int o = 16; o; o >>= 1) mx = fmaxf(mx, __shfl_xor_sync(0xffffffffu, mx, o));
        float e0 = __expf(x0 - mx);
        float e1 = (lane == 0) ? __expf(x1 - mx) : 0.f;
        float s = e0 + e1;
        #pragma unroll
        for (int o = 16; o; o >>= 1) s += __shfl_xor_sync(0xffffffffu, s, o);
        float inv = 1.f / s;
        rowp[lane] = e0 * inv;
        if (lane == 0) rowp[32] = e1 * inv;
    }
    __syncthreads();

    int h = (tid >> 5) & 7, d = lane, pair = tid >> 8;
    const float* vbase = sq + 2 * CCH + h * HDIM + d;
    __half* ob = outbuf + ((size_t)m * TOK) * CCH + h * HDIM + d;
    for (int i = pair; i < TOK; i += 2) {
        const float* srow = sscore + (h * TOK + i) * TOK;
        float acc = 0.f;
        #pragma unroll
        for (int j = 0; j < TOK; j++) acc += srow[j] * vbase[(size_t)j * C3];
        ob[(size_t)i * CCH] = __float2half(acc);
    }
}

// ---------------- host launcher ----------------
extern "C" void kernel_launch(void* const* d_in, const int* in_sizes, int n_in,
                              void* d_out, int out_size)
{
    const float* data      = (const float*)d_in[0];
    const float* rt        = (const float*)d_in[1];
    const int*   neighbors = (const int*)  d_in[2];
    const int*   rel_pos   = (const int*)  d_in[3];
    const float* mask      = (const float*)d_in[4];
    const float* cpe_w     = (const float*)d_in[5];
    const float* cpe_scale = (const float*)d_in[6];
    const float* cpe_bias  = (const float*)d_in[7];
    const float* ln1_g     = (const float*)d_in[8];
    const float* ln1_b     = (const float*)d_in[9];
    const float* qkv_w     = (const float*)d_in[10];
    const float* qkv_b     = (const float*)d_in[11];
    const float* rpe_table = (const float*)d_in[12];
    const float* proj_w    = (const float*)d_in[13];
    const float* proj_b    = (const float*)d_in[14];
    const float* ln2_g     = (const float*)d_in[15];
    const float* ln2_b     = (const float*)d_in[16];
    const float* mlp_w1    = (const float*)d_in[17];
    const float* mlp_b1    = (const float*)d_in[18];
    const float* mlp_w2    = (const float*)d_in[19];
    const float* mlp_b2    = (const float*)d_in[20];
    float* out = (float*)d_out;

    float*  xbuf;  cudaGetSymbolAddress((void**)&xbuf,  g_xbuf);
    __half* hbuf;  cudaGetSymbolAddress((void**)&hbuf,  g_hbuf16);
    __half* big;   cudaGetSymbolAddress((void**)&big,   g_big16);
    __half* wT;    cudaGetSymbolAddress((void**)&wT,    g_wT16);

    __half* qkvT  = wT;
    __half* projT = qkvT + 768 * 256;
    __half* mlp1T = projT + 256 * 256;
    __half* mlp2T = mlp1T + 1024 * 256;

    cudaFuncSetAttribute(attn_kernel, cudaFuncAttributeMaxDynamicSharedMemorySize, ATTN_SMEM);
    cudaFuncSetAttribute(hgemm<0, __half>, cudaFuncAttributeMaxDynamicSharedMemorySize, GEMM_SMEM);
    cudaFuncSetAttribute(hgemm<1, float>,  cudaFuncAttributeMaxDynamicSharedMemorySize, GEMM_SMEM);
    cudaFuncSetAttribute(hgemm<2, __half>, cudaFuncAttributeMaxDynamicSharedMemorySize, GEMM_SMEM);
    cudaFuncSetAttribute(hgemm<3, float>,  cudaFuncAttributeMaxDynamicSharedMemorySize, GEMM_SMEM);

    // 0. weight transposes + data fp16 mirror
    wt_kernel<<<dim3(768/32, 256/32),  256>>>(qkv_w,  qkvT,  256, 768);
    wt_kernel<<<dim3(256/32, 256/32),  256>>>(proj_w, projT, 256, 256);
    wt_kernel<<<dim3(1024/32, 256/32), 256>>>(mlp_w1, mlp1T, 256, 1024);
    wt_kernel<<<dim3(256/32, 1024/32), 256>>>(mlp_w2, mlp2T, 1024, 256);
    cvt_data_kernel<<<(NPTS * CCH) / (256 * 4), 256>>>(data);

    // 1. CPE + residual -> x
    cpe_kernel<<<NPTS + MWIN, 128>>>(data, rt, neighbors, cpe_w, cpe_scale, cpe_bias);

    // 2. LN1 -> fp16
    ln_kernel<<<ROWS / 8, 256>>>(xbuf, hbuf, ln1_g, ln1_b);

    // 3. QKV (fp16 out)
    hgemm<0, __half><<<dim3(C3/256, ROWS/128), 256, GEMM_SMEM>>>(
        hbuf, qkvT, qkv_b, big, nullptr, CCH, C3);

    // 4. attention -> fp16
    attn_kernel<<<MWIN, ATTN_THREADS, ATTN_SMEM>>>(big, rel_pos, mask, rpe_table, hbuf);

    // 5. x += attnout @ proj (fp32 residual)
    hgemm<1, float><<<dim3(CCH/256, ROWS/128), 256, GEMM_SMEM>>>(
        hbuf, projT, proj_b, xbuf, xbuf, CCH, CCH);

    // 6. LN2 -> fp16
    ln_kernel<<<ROWS / 8, 256>>>(xbuf, hbuf, ln2_g, ln2_b);

    // 7. hidden = gelu(h @ mlp_w1) (fp16 out)
    hgemm<2, __half><<<dim3(HID/256, ROWS/128), 256, GEMM_SMEM>>>(
        hbuf, mlp1T, mlp_b1, big, nullptr, CCH, HID);

    // 8. out = x + hidden @ mlp_w2 (scattered, fp32)
    hgemm<3, float><<<dim3(CCH/256, ROWS/128), 256, GEMM_SMEM>>>(
        big, mlp2T, mlp_b2, out, xbuf, HID, CCH);
}

// round 7
// speedup vs baseline: 4.0570x; 1.1771x over previous
#include <cuda_runtime.h>
#include <cuda_fp16.h>
#include <math.h>
#include <stdint.h>

// ---------------- problem constants ----------------
#define MWIN   8192
#define KTOK   32
#define TOK    33          // K + G
#define CCH    256
#define HEADS  8
#define HDIM   32
#define NPTS   (MWIN * KTOK)        // 262144
#define ROWS   (MWIN * TOK)         // 270336
#define HID    1024
#define NEIGH  27
#define POS_BND 25
#define RPE_NUM 51
#define C3     768

// ---------------- scratch ----------------
__device__ float  g_xbuf [(size_t)ROWS * CCH];   // residual stream (fp32)
__device__ __half g_hbuf16[(size_t)ROWS * CCH];  // LN out / attn out (fp16)
__device__ __half g_big16 [(size_t)ROWS * HID];  // qkv / mlp hidden (fp16)
__device__ __half g_wT16  [768*256 + 256*256 + 1024*256 + 256*1024]; // W^T fp16
__device__ __half g_data16[(size_t)NPTS * CCH];  // fp16 mirror of data for gather

// ---------------- PTX helpers ----------------
__device__ __forceinline__ uint32_t smem_u32(const void* p) {
    uint32_t a;
    asm("{ .reg .u64 t; cvta.to.shared.u64 t, %1; cvt.u32.u64 %0, t; }" : "=r"(a) : "l"(p));
    return a;
}
#define CP_ASYNC16(dst_u32, src_ptr) \
    asm volatile("cp.async.cg.shared.global [%0], [%1], 16;\n" :: "r"(dst_u32), "l"(src_ptr))
#define CP_COMMIT() asm volatile("cp.async.commit_group;\n")
#define CP_WAIT(n)  asm volatile("cp.async.wait_group %0;\n" :: "n"(n))

#define LDSM_X4(r0,r1,r2,r3,a) \
    asm volatile("ldmatrix.sync.aligned.m8n8.x4.shared.b16 {%0,%1,%2,%3}, [%4];" \
        : "=r"(r0),"=r"(r1),"=r"(r2),"=r"(r3) : "r"(a))

#define HMMA16816(d, a, b) \
    asm volatile("mma.sync.aligned.m16n8k16.row.col.f32.f16.f16.f32 " \
        "{%0,%1,%2,%3},{%4,%5,%6,%7},{%8,%9},{%0,%1,%2,%3};" \
        : "+f"((d)[0]),"+f"((d)[1]),"+f"((d)[2]),"+f"((d)[3]) \
        : "r"((a)[0]),"r"((a)[1]),"r"((a)[2]),"r"((a)[3]),"r"((b)[0]),"r"((b)[1]))

// ---------------- weight transpose: in[K][N] fp32 -> out[N][K] fp16 ----------------
__global__ void __launch_bounds__(256) wt_kernel(const float* __restrict__ in,
                                                 __half* __restrict__ out, int K, int N)
{
    __shared__ float tile[32][33];
    int bx = blockIdx.x * 32, by = blockIdx.y * 32;
    int x = threadIdx.x & 31, y = threadIdx.x >> 5;
    #pragma unroll
    for (int i = 0; i < 32; i += 8)
        tile[y + i][x] = in[(size_t)(by + y + i) * N + bx + x];
    __syncthreads();
    #pragma unroll
    for (int i = 0; i < 32; i += 8)
        out[(size_t)(bx + y + i) * K + by + x] = __float2half(tile[x][y + i]);
}

// ---------------- data -> fp16 mirror ----------------
__global__ void __launch_bounds__(256) cvt_data_kernel(const float* __restrict__ data)
{
    size_t i = ((size_t)blockIdx.x * 256 + threadIdx.x) * 4;
    float4 f = *(const float4*)(data + i);
    __half2* d = (__half2*)(g_data16 + i);
    d[0] = __floats2half2_rn(f.x, f.y);
    d[1] = __floats2half2_rn(f.z, f.w);
}

// ---------------- CPE gather + residual + fused LN1 ----------------
// one block (128 threads) = one row; writes xbuf fp32 + hbuf fp16 (LN'd)
__global__ void __launch_bounds__(128) cpe_ln_kernel(
    const float* __restrict__ data, const float* __restrict__ rt,
    const int* __restrict__ neighbors, const float* __restrict__ cpe_w,
    const float* __restrict__ cpe_scale, const float* __restrict__ cpe_bias,
    const float* __restrict__ gam, const float* __restrict__ bet)
{
    __shared__ int nb[NEIGH];
    __shared__ float red[8];
    int bid = blockIdx.x;
    int tid = threadIdx.x;
    int c = tid * 2;
    float2 v;
    size_t row;

    if (bid >= NPTS) {
        int m = bid - NPTS;
        row = (size_t)m * TOK;
        v = *(const float2*)(rt + (size_t)m * CCH + c);
    } else {
        if (tid < NEIGH) nb[tid] = neighbors[(size_t)bid * NEIGH + tid];
        __syncthreads();
        float ax = 0.f, ay = 0.f;
        #pragma unroll
        for (int j = 0; j < NEIGH; j++) {
            __half2 h = *(const __half2*)(g_data16 + (size_t)nb[j] * CCH + c);
            float2 f = __half22float2(h);
            float2 w = *(const float2*)(cpe_w + j * CCH + c);
            ax += f.x * w.x; ay += f.y * w.y;
        }
        float2 d0 = *(const float2*)(data + (size_t)bid * CCH + c);
        float2 sc = *(const float2*)(cpe_scale + c);
        float2 bi = *(const float2*)(cpe_bias + c);
        v = make_float2(d0.x + ax * sc.x + bi.x, d0.y + ay * sc.y + bi.y);
        int m = bid >> 5, k = bid & 31;
        row = (size_t)m * TOK + 1 + k;
    }
    *(float2*)(g_xbuf + row * CCH + c) = v;

    // LN over the 256 channels
    float s1 = v.x + v.y;
    float s2 = v.x * v.x + v.y * v.y;
    #pragma unroll
    for (int o = 16; o; o >>= 1) {
        s1 += __shfl_xor_sync(0xffffffffu, s1, o);
        s2 += __shfl_xor_sync(0xffffffffu, s2, o);
    }
    int warp = tid >> 5, lane = tid & 31;
    if (lane == 0) { red[warp] = s1; red[4 + warp] = s2; }
    __syncthreads();
    s1 = red[0] + red[1] + red[2] + red[3];
    s2 = red[4] + red[5] + red[6] + red[7];
    float mean = s1 * (1.f / 256.f);
    float var = s2 * (1.f / 256.f) - mean * mean;
    float rstd = rsqrtf(var + 1e-5f);
    float2 gm = *(const float2*)(gam + c);
    float2 bt = *(const float2*)(bet + c);
    *(__half2*)(g_hbuf16 + row * CCH + c) = __floats2half2_rn(
        (v.x - mean) * rstd * gm.x + bt.x, (v.y - mean) * rstd * gm.y + bt.y);
}

// ---------------- fp16 tensor-core GEMM: CTA 128x256, warp tile 64x64 ----------------
// MODE 0: half out = A@B+bias
// MODE 2: half out = gelu(A@B+bias)
// MODE 3: float out = res + A@B+bias, scattered into d_out layout
// MODE 4: float out = res + A@B+bias (xbuf), plus fused LN -> hout fp16 (needs grid.x==1)
#define A_TILE   10240            // 128 rows * 80 bytes
#define B_TILE   20480            // 256 rows * 80 bytes
#define GEMM_SMEM (3 * (A_TILE + B_TILE))   // 92160

template<int MODE, typename OutT>
__global__ void __launch_bounds__(256) hgemm(
    const __half* __restrict__ A, const __half* __restrict__ Bt,
    const float* __restrict__ bias, OutT* __restrict__ Cout,
    const float* __restrict__ res, int Kdim, int Ndim,
    const float* __restrict__ gam, const float* __restrict__ bet,
    __half* __restrict__ hout)
{
    extern __shared__ char smraw[];
    uint32_t base = smem_u32(smraw);
    float* lnsum = (float*)smraw;          // reused after mainloop (MODE 4)
    float* lnsq  = (float*)smraw + 128;

    int tid = threadIdx.x;
    int warp = tid >> 5, lane = tid & 31;
    int wm = (warp >> 2) * 64;
    int wn = (warp & 3) * 64;
    int la = lane & 7, grp = lane >> 3;
    int g = lane >> 2, t = lane & 3;

    size_t rowBase = (size_t)blockIdx.y * 128;
    int colBase = blockIdx.x * 256;

    const __half* Ag = A  + rowBase * Kdim;
    const __half* Bg = Bt + (size_t)colBase * Kdim;

    int aRow = la + (grp & 1) * 8;
    int aKof = (grp >> 1) * 8;
    int bRow = la + (grp >> 1) * 8;
    int bKof = (grp & 1) * 8;

    float acc[4][8][4];
    #pragma unroll
    for (int mt = 0; mt < 4; mt++)
        #pragma unroll
        for (int nt = 0; nt < 8; nt++)
            #pragma unroll
            for (int i = 0; i < 4; i++) acc[mt][nt][i] = 0.f;

    auto loadStage = [&](int s, int k0) {
        #pragma unroll
        for (int i = 0; i < 2; i++) {
            int idx = i * 256 + tid;
            int row = idx >> 2, c = idx & 3;
            CP_ASYNC16(base + s * A_TILE + row * 80 + c * 16,
                       Ag + (size_t)row * Kdim + k0 + c * 8);
        }
        #pragma unroll
        for (int i = 0; i < 4; i++) {
            int idx = i * 256 + tid;
            int row = idx >> 2, c = idx & 3;
            CP_ASYNC16(base + 3 * A_TILE + s * B_TILE + row * 80 + c * 16,
                       Bg + (size_t)row * Kdim + k0 + c * 8);
        }
    };

    int KT = Kdim >> 5;
    loadStage(0, 0);  CP_COMMIT();
    loadStage(1, 32); CP_COMMIT();

    for (int kt = 0; kt < KT; kt++) {
        if (kt + 1 < KT) CP_WAIT(1); else CP_WAIT(0);
        __syncthreads();
        if (kt + 2 < KT) { loadStage((kt + 2) % 3, (kt + 2) << 5); CP_COMMIT(); }

        int buf = kt % 3;
        uint32_t aBase = base + buf * A_TILE;
        uint32_t bBase = base + 3 * A_TILE + buf * B_TILE;

        #pragma unroll
        for (int kk = 0; kk < 2; kk++) {
            int kb = kk * 16;
            uint32_t af[4][4], bf[8][2];
            #pragma unroll
            for (int mt = 0; mt < 4; mt++) {
                uint32_t ad = aBase + (uint32_t)(wm + mt * 16 + aRow) * 80
                            + (uint32_t)(kb + aKof) * 2;
                LDSM_X4(af[mt][0], af[mt][1], af[mt][2], af[mt][3], ad);
            }
            #pragma unroll
            for (int np = 0; np < 4; np++) {
                uint32_t bd = bBase + (uint32_t)(wn + np * 16 + bRow) * 80
                            + (uint32_t)(kb + bKof) * 2;
                LDSM_X4(bf[2*np][0], bf[2*np][1], bf[2*np+1][0], bf[2*np+1][1], bd);
            }
            #pragma unroll
            for (int mt = 0; mt < 4; mt++)
                #pragma unroll
                for (int nt = 0; nt < 8; nt++)
                    HMMA16816(acc[mt][nt], af[mt], bf[nt]);
        }
    }

    if (MODE == 4) {
        __syncthreads();
        if (tid < 128) { lnsum[tid] = 0.f; }
        else { lnsq[tid - 128] = 0.f; }
        __syncthreads();
    }

    // epilogue: pairs (2t,2t+1) consecutive cols -> vector stores
    #pragma unroll
    for (int mt = 0; mt < 4; mt++) {
        #pragma unroll
        for (int nt = 0; nt < 8; nt++) {
            int col = colBase + wn + nt * 8 + 2 * t;
            float b0 = bias[col], b1 = bias[col + 1];
            #pragma unroll
            for (int hf = 0; hf < 2; hf++) {
                size_t row = rowBase + wm + mt * 16 + g + hf * 8;
                float v0 = acc[mt][nt][hf * 2 + 0] + b0;
                float v1 = acc[mt][nt][hf * 2 + 1] + b1;
                if (MODE == 0) {
                    *(__half2*)&((__half*)Cout)[row * Ndim + col] =
                        __floats2half2_rn(v0, v1);
                } else if (MODE == 2) {
                    v0 = 0.5f * v0 * (1.0f + erff(v0 * 0.70710678118654752f));
                    v1 = 0.5f * v1 * (1.0f + erff(v1 * 0.70710678118654752f));
                    *(__half2*)&((__half*)Cout)[row * Ndim + col] =
                        __floats2half2_rn(v0, v1);
                } else if (MODE == 3) {
                    const float2 r2 = *(const float2*)&res[row * CCH + col];
                    size_t m = row / TOK;
                    int tt = (int)(row - m * TOK);
                    float* dst = (tt == 0)
                        ? ((float*)Cout + (size_t)NPTS * CCH + m * CCH + col)
                        : ((float*)Cout + (m * KTOK + (size_t)(tt - 1)) * CCH + col);
                    *(float2*)dst = make_float2(v0 + r2.x, v1 + r2.y);
                } else { // MODE 4
                    const float2 r2 = *(const float2*)&res[row * Ndim + col];
                    v0 += r2.x; v1 += r2.y;
                    acc[mt][nt][hf * 2 + 0] = v0;
                    acc[mt][nt][hf * 2 + 1] = v1;
                    *(float2*)&((float*)Cout)[row * Ndim + col] = make_float2(v0, v1);
                }
            }
        }
    }

    if (MODE == 4) {
        // per-row partial sums (quad-reduce over t, atomics across warps)
        #pragma unroll
        for (int mt = 0; mt < 4; mt++) {
            #pragma unroll
            for (int hf = 0; hf < 2; hf++) {
                int rloc = wm + mt * 16 + g + hf * 8;
                float s1 = 0.f, s2 = 0.f;
                #pragma unroll
                for (int nt = 0; nt < 8; nt++) {
                    float v0 = acc[mt][nt][hf * 2 + 0];
                    float v1 = acc[mt][nt][hf * 2 + 1];
                    s1 += v0 + v1;
                    s2 += v0 * v0 + v1 * v1;
                }
                s1 += __shfl_xor_sync(0xffffffffu, s1, 1);
                s1 += __shfl_xor_sync(0xffffffffu, s1, 2);
                s2 += __shfl_xor_sync(0xffffffffu, s2, 1);
                s2 += __shfl_xor_sync(0xffffffffu, s2, 2);
                if (t == 0) {
                    atomicAdd(&lnsum[rloc], s1);
                    atomicAdd(&lnsq[rloc],  s2);
                }
            }
        }
        __syncthreads();
        #pragma unroll
        for (int mt = 0; mt < 4; mt++) {
            #pragma unroll
            for (int hf = 0; hf < 2; hf++) {
                int rloc = wm + mt * 16 + g + hf * 8;
                size_t row = rowBase + rloc;
                float mean = lnsum[rloc] * (1.f / 256.f);
                float var  = lnsq[rloc] * (1.f / 256.f) - mean * mean;
                float rstd = rsqrtf(var + 1e-5f);
                #pragma unroll
                for (int nt = 0; nt < 8; nt++) {
                    int col = wn + nt * 8 + 2 * t;
                    float v0 = acc[mt][nt][hf * 2 + 0];
                    float v1 = acc[mt][nt][hf * 2 + 1];
                    float o0 = (v0 - mean) * rstd * gam[col]     + bet[col];
                    float o1 = (v1 - mean) * rstd * gam[col + 1] + bet[col + 1];
                    *(__half2*)&hout[row * CCH + col] = __floats2half2_rn(o0, o1);
                }
            }
        }
    }
}

// ---------------- fused per-window attention (fp16 smem, 2 CTA/SM) ----------------
#define ATTN_THREADS 512
#define SQH_H  (TOK * C3)                 // 25344 halves = 50688 B
#define KT2_E  ((CCH / 2) * TOK)          // 4224 half2  = 16896 B
#define SC_F   (HEADS * TOK * TOK)        // 8712 floats = 34848 B
#define TAB_F  (3 * RPE_NUM * HEADS)      // 1224 floats = 4896 B
#define ATTN_SMEM (SQH_H * 2 + KT2_E * 4 + SC_F * 4 + TAB_F * 4)   // 107328

__global__ void __launch_bounds__(ATTN_THREADS) attn_kernel(
    const __half* __restrict__ qkv, const int* __restrict__ rel_pos,
    const float* __restrict__ mask, const float* __restrict__ rpe_table,
    __half* __restrict__ outbuf)
{
    extern __shared__ char smc[];
    __half*  sqh    = (__half*)smc;                       // [TOK*C3]
    __half2* ktb2   = (__half2*)(smc + SQH_H * 2);        // [CCH/2][TOK]
    float*   sscore = (float*)(smc + SQH_H * 2 + KT2_E * 4);
    float*   stab   = sscore + SC_F;

    int m = blockIdx.x, tid = threadIdx.x;
    const __half2* src = (const __half2*)(qkv + (size_t)m * TOK * C3);
    __half2* dsq = (__half2*)sqh;
    for (int i = tid; i < SQH_H / 2; i += ATTN_THREADS) dsq[i] = src[i];
    for (int i = tid; i < TAB_F; i += ATTN_THREADS) stab[i] = rpe_table[i];
    __syncthreads();

    // transpose K as half2 pairs: ktb2[c2][j] = (k[2c2][j], k[2c2+1][j])
    for (int idx = tid; idx < KT2_E; idx += ATTN_THREADS) {
        int c2 = idx & 127, j = idx >> 7;
        ktb2[c2 * TOK + j] = *(const __half2*)(sqh + j * C3 + CCH + c2 * 2);
    }
    __syncthreads();

    const float scale = 0.17677669529663687f;

    for (int idx = tid; idx < SC_F; idx += ATTN_THREADS) {
        int j = idx % TOK;
        int ih = idx / TOK;
        int i = ih % TOK;
        int h = ih / TOK;
        const __half2* qp = (const __half2*)(sqh + i * C3 + h * HDIM);
        const __half2* kp = ktb2 + (h * 16) * TOK + j;
        float s = 0.f;
        #pragma unroll
        for (int d2 = 0; d2 < 16; d2++) {
            float2 q2 = __half22float2(qp[d2]);
            float2 k2 = __half22float2(kp[d2 * TOK]);
            s += q2.x * k2.x + q2.y * k2.y;
        }
        s *= scale;
        if (i > 0 && j > 0) {
            const int* rp = rel_pos + (((size_t)m * KTOK + (i - 1)) * KTOK + (j - 1)) * 3;
            #pragma unroll
            for (int dd = 0; dd < 3; dd++) {
                int r = rp[dd];
                r = min(max(r, -POS_BND), POS_BND);
                s += stab[(r + POS_BND + dd * RPE_NUM) * HEADS + h];
            }
        }
        s += mask[((size_t)m * TOK + i) * TOK + j];
        sscore[(h * TOK + i) * TOK + j] = s;
    }
    __syncthreads();

    int lane = tid & 31, warp = tid >> 5;
    for (int r = warp; r < HEADS * TOK; r += 16) {
        float* rowp = sscore + r * TOK;
        float x0 = rowp[lane];
        float x1 = (lane == 0) ? rowp[32] : -1e30f;
        float mx = fmaxf(x0, x1);
        #pragma unroll
        for (int o = 16; o; o >>= 1) mx = fmaxf(mx, __shfl_xor_sync(0xffffffffu, mx, o));
        float e0 = __expf(x0 - mx);
        float e1 = (lane == 0) ? __expf(x1 - mx) : 0.f;
        float s = e0 + e1;
        #pragma unroll
        for (int o = 16; o; o >>= 1) s += __shfl_xor_sync(0xffffffffu, s, o);
        float inv = 1.f / s;
        rowp[lane] = e0 * inv;
        if (lane == 0) rowp[32] = e1 * inv;
    }
    __syncthreads();

    int h = (tid >> 5) & 7, d = lane, pair = tid >> 8;
    const __half* vb = sqh + 2 * CCH + h * HDIM + d;
    __half* ob = outbuf + ((size_t)m * TOK) * CCH + h * HDIM + d;
    for (int i = pair; i < TOK; i += 2) {
        const float* srow = sscore + (h * TOK + i) * TOK;
        float acc = 0.f;
        #pragma unroll
        for (int j = 0; j < TOK; j++) acc += srow[j] * __half2float(vb[(size_t)j * C3]);
        ob[(size_t)i * CCH] = __float2half(acc);
    }
}

// ---------------- host launcher ----------------
extern "C" void kernel_launch(void* const* d_in, const int* in_sizes, int n_in,
                              void* d_out, int out_size)
{
    const float* data      = (const float*)d_in[0];
    const float* rt        = (const float*)d_in[1];
    const int*   neighbors = (const int*)  d_in[2];
    const int*   rel_pos   = (const int*)  d_in[3];
    const float* mask      = (const float*)d_in[4];
    const float* cpe_w     = (const float*)d_in[5];
    const float* cpe_scale = (const float*)d_in[6];
    const float* cpe_bias  = (const float*)d_in[7];
    const float* ln1_g     = (const float*)d_in[8];
    const float* ln1_b     = (const float*)d_in[9];
    const float* qkv_w     = (const float*)d_in[10];
    const float* qkv_b     = (const float*)d_in[11];
    const float* rpe_table = (const float*)d_in[12];
    const float* proj_w    = (const float*)d_in[13];
    const float* proj_b    = (const float*)d_in[14];
    const float* ln2_g     = (const float*)d_in[15];
    const float* ln2_b     = (const float*)d_in[16];
    const float* mlp_w1    = (const float*)d_in[17];
    const float* mlp_b1    = (const float*)d_in[18];
    const float* mlp_w2    = (const float*)d_in[19];
    const float* mlp_b2    = (const float*)d_in[20];
    float* out = (float*)d_out;

    float*  xbuf;  cudaGetSymbolAddress((void**)&xbuf,  g_xbuf);
    __half* hbuf;  cudaGetSymbolAddress((void**)&hbuf,  g_hbuf16);
    __half* big;   cudaGetSymbolAddress((void**)&big,   g_big16);
    __half* wT;    cudaGetSymbolAddress((void**)&wT,    g_wT16);

    __half* qkvT  = wT;
    __half* projT = qkvT + 768 * 256;
    __half* mlp1T = projT + 256 * 256;
    __half* mlp2T = mlp1T + 1024 * 256;

    cudaFuncSetAttribute(attn_kernel, cudaFuncAttributeMaxDynamicSharedMemorySize, ATTN_SMEM);
    cudaFuncSetAttribute(hgemm<0, __half>, cudaFuncAttributeMaxDynamicSharedMemorySize, GEMM_SMEM);
    cudaFuncSetAttribute(hgemm<2, __half>, cudaFuncAttributeMaxDynamicSharedMemorySize, GEMM_SMEM);
    cudaFuncSetAttribute(hgemm<3, float>,  cudaFuncAttributeMaxDynamicSharedMemorySize, GEMM_SMEM);
    cudaFuncSetAttribute(hgemm<4, float>,  cudaFuncAttributeMaxDynamicSharedMemorySize, GEMM_SMEM);

    // 0. weight transposes + data fp16 mirror
    wt_kernel<<<dim3(768/32, 256/32),  256>>>(qkv_w,  qkvT,  256, 768);
    wt_kernel<<<dim3(256/32, 256/32),  256>>>(proj_w, projT, 256, 256);
    wt_kernel<<<dim3(1024/32, 256/32), 256>>>(mlp_w1, mlp1T, 256, 1024);
    wt_kernel<<<dim3(256/32, 1024/32), 256>>>(mlp_w2, mlp2T, 1024, 256);
    cvt_data_kernel<<<(NPTS * CCH) / (256 * 4), 256>>>(data);

    // 1. CPE + residual + LN1 -> xbuf (fp32) + hbuf (fp16)
    cpe_ln_kernel<<<NPTS + MWIN, 128>>>(data, rt, neighbors, cpe_w, cpe_scale,
                                        cpe_bias, ln1_g, ln1_b);

    // 2. QKV (fp16 out)
    hgemm<0, __half><<<dim3(C3/256, ROWS/128), 256, GEMM_SMEM>>>(
        hbuf, qkvT, qkv_b, big, nullptr, CCH, C3, nullptr, nullptr, nullptr);

    // 3. attention -> hbuf fp16
    attn_kernel<<<MWIN, ATTN_THREADS, ATTN_SMEM>>>(big, rel_pos, mask, rpe_table, hbuf);

    // 4. proj + residual + fused LN2: xbuf fp32 + hbuf fp16
    hgemm<4, float><<<dim3(1, ROWS/128), 256, GEMM_SMEM>>>(
        hbuf, projT, proj_b, xbuf, xbuf, CCH, CCH, ln2_g, ln2_b, hbuf);

    // 5. hidden = gelu(h @ mlp_w1) (fp16 out)
    hgemm<2, __half><<<dim3(HID/256, ROWS/128), 256, GEMM_SMEM>>>(
        hbuf, mlp1T, mlp_b1, big, nullptr, CCH, HID, nullptr, nullptr, nullptr);

    // 6. out = x + hidden @ mlp_w2 (scattered, fp32)
    hgemm<3, float><<<dim3(CCH/256, ROWS/128), 256, GEMM_SMEM>>>(
        big, mlp2T, mlp_b2, out, xbuf, HID, CCH, nullptr, nullptr, nullptr);
}